// round 15
// baseline (speedup 1.0000x reference)
#include <cuda_runtime.h>
#include <cstdint>
#include <cmath>

#define B_    2
#define L_    2048
#define DM_   2048
#define DIP_  8512
#define DI_   4096
#define CDIM_ 4352
#define NH_   64
#define HD_   64
#define DS_   128
#define CH_   256
#define NC_   8
#define DCV   4
#define GN_   8448
#define KSPL  32

// ---------------- scratch ----------------
__device__ float g_zx  [(size_t)B_*L_*DIP_];
__device__ float g_xBC [(size_t)B_*L_*CDIM_];
__device__ float g_dtv [(size_t)B_*L_*NH_];
__device__ float g_dtp [(size_t)KSPL*B_*L_*NH_];
__device__ float g_Acs [(size_t)B_*NC_*NH_*CH_];
__device__ float g_CB  [(size_t)B_*NC_*CH_*CH_];
__device__ float g_st  [(size_t)B_*NC_*NH_*HD_*DS_];
__device__ float g_is  [(size_t)B_*NC_*NH_*HD_*DS_];
__device__ float g_y   [(size_t)B_*L_*DI_];

__device__ __forceinline__ float f2tf32f(float x) {
    uint32_t r;
    asm("cvt.rna.tf32.f32 %0, %1;" : "=r"(r) : "f"(x));
    return __uint_as_float(r);
}
__device__ __forceinline__ uint32_t f2tf32u(float x) {
    uint32_t r;
    asm("cvt.rna.tf32.f32 %0, %1;" : "=r"(r) : "f"(x));
    return r;
}
__device__ __forceinline__ uint32_t smem_u32(const void* p) {
    uint32_t a;
    asm("{ .reg .u64 t; cvta.to.shared.u64 t, %1; cvt.u32.u64 %0, t; }" : "=r"(a) : "l"(p));
    return a;
}
__device__ __forceinline__ void cpa16(uint32_t dst, const void* src) {
    asm volatile("cp.async.cg.shared.global [%0], [%1], 16;" :: "r"(dst), "l"(src));
}
#define CPA_COMMIT() asm volatile("cp.async.commit_group;" ::: "memory")
#define CPA_WAIT1()  asm volatile("cp.async.wait_group 1;" ::: "memory")
#define MMA_TF32(acc, a0,a1,a2,a3, b0,b1)                                      \
    asm volatile("mma.sync.aligned.m16n8k8.row.col.f32.tf32.tf32.f32 "         \
        "{%0,%1,%2,%3}, {%4,%5,%6,%7}, {%8,%9}, {%0,%1,%2,%3};"                \
        : "+f"((acc)[0]), "+f"((acc)[1]), "+f"((acc)[2]), "+f"((acc)[3])       \
        : "r"(a0), "r"(a1), "r"(a2), "r"(a3), "r"(b0), "r"(b1))

// ---------------- K1: main tf32 GEMM, 3-stage cp.async, inline tf32 cvt ------
// raw u/w streamed directly; cvt.rna at fragment load (ALU pipe idle under HMMA)
#define ASTG 18432
#define BSTG 33792
#define STG_ (ASTG + BSTG)
__global__ __launch_bounds__(256, 1) void gemm_tf32_kernel(const float* __restrict__ u,
                                                           const float* __restrict__ w) {
    extern __shared__ char sal[];
    const int tid = threadIdx.x;
    const int m0 = blockIdx.y * 128;
    const int n0 = blockIdx.x * 256;
    const int lane = tid & 31, wid = tid >> 5;
    const int wm = wid >> 2, wn = wid & 3;
    const int grp = lane >> 2, tig = lane & 3;
    const uint32_t sbase = smem_u32(sal);
    const int NKT = DM_ / 32;

    float acc[4][8][4];
#pragma unroll
    for (int mt = 0; mt < 4; mt++)
#pragma unroll
        for (int nt = 0; nt < 8; nt++)
#pragma unroll
            for (int i = 0; i < 4; i++) acc[mt][nt][i] = 0.f;

    auto issue = [&](int buf, int kt) {
        uint32_t ab = sbase + buf * STG_;
        uint32_t bb = ab + ASTG;
#pragma unroll
        for (int i = 0; i < 4; i++) {
            int slot = tid + i * 256;
            int row = slot >> 3, c = slot & 7;
            cpa16(ab + row * 144 + c * 16,
                  u + (size_t)(m0 + row) * DM_ + kt * 32 + c * 4);
        }
#pragma unroll
        for (int i = 0; i < 8; i++) {
            int slot = tid + i * 256;
            int row = slot >> 6, c = slot & 63;
            cpa16(bb + row * 1056 + c * 16,
                  w + (size_t)(kt * 32 + row) * DIP_ + n0 + c * 4);
        }
    };

    issue(0, 0); CPA_COMMIT();
    issue(1, 1); CPA_COMMIT();

    for (int kt = 0; kt < NKT; kt++) {
        CPA_WAIT1();
        __syncthreads();
        if (kt + 2 < NKT) issue((kt + 2) % 3, kt + 2);
        CPA_COMMIT();

        const float* As = (const float*)(sal + (kt % 3) * STG_);
        const float* Bs = (const float*)(sal + (kt % 3) * STG_ + ASTG);
#pragma unroll
        for (int ks = 0; ks < 4; ks++) {
            uint32_t a[4][4], b[8][2];
#pragma unroll
            for (int mt = 0; mt < 4; mt++) {
                int r0 = wm * 64 + mt * 16 + grp;
                a[mt][0] = f2tf32u(As[r0 * 36 + ks * 8 + tig]);
                a[mt][1] = f2tf32u(As[(r0 + 8) * 36 + ks * 8 + tig]);
                a[mt][2] = f2tf32u(As[r0 * 36 + ks * 8 + tig + 4]);
                a[mt][3] = f2tf32u(As[(r0 + 8) * 36 + ks * 8 + tig + 4]);
            }
#pragma unroll
            for (int nt = 0; nt < 8; nt++) {
                int cc = wn * 64 + nt * 8 + grp;
                b[nt][0] = f2tf32u(Bs[(ks * 8 + tig) * 264 + cc]);
                b[nt][1] = f2tf32u(Bs[(ks * 8 + tig + 4) * 264 + cc]);
            }
#pragma unroll
            for (int mt = 0; mt < 4; mt++)
#pragma unroll
                for (int nt = 0; nt < 8; nt++)
                    MMA_TF32(acc[mt][nt], a[mt][0], a[mt][1], a[mt][2], a[mt][3],
                             b[nt][0], b[nt][1]);
        }
        __syncthreads();
    }

#pragma unroll
    for (int mt = 0; mt < 4; mt++)
#pragma unroll
        for (int nt = 0; nt < 8; nt++) {
            int row = m0 + wm * 64 + mt * 16 + grp;
            int col = n0 + wn * 64 + nt * 8 + tig * 2;
            float2 v0, v1;
            v0.x = acc[mt][nt][0]; v0.y = acc[mt][nt][1];
            v1.x = acc[mt][nt][2]; v1.y = acc[mt][nt][3];
            *(float2*)&g_zx[(size_t)row * DIP_ + col]       = v0;
            *(float2*)&g_zx[(size_t)(row + 8) * DIP_ + col] = v1;
        }
}

// ---------------- K1b: dt GEMM K-split (KSPL=32, proven) ----------------
__global__ __launch_bounds__(256) void dtg_part_kernel(const float* __restrict__ u,
                                                       const float* __restrict__ w) {
    __shared__ float u_s[32][136];
    __shared__ float w_s[32][68];
    const int m0 = blockIdx.x * 128;
    const int k0 = blockIdx.y * 64;
    const int tid = threadIdx.x;
    const int ti = tid >> 4, ni = tid & 15;
    float acc[8][4];
#pragma unroll
    for (int i = 0; i < 8; i++)
#pragma unroll
        for (int j = 0; j < 4; j++) acc[i][j] = 0.f;

    for (int kt = 0; kt < 64; kt += 32) {
        __syncthreads();
#pragma unroll
        for (int i = 0; i < 4; i++) {
            int slot = tid + i * 256;
            int row = slot >> 3, kq = (slot & 7) << 2;
            float4 v = *(const float4*)(u + (size_t)(m0 + row) * DM_ + k0 + kt + kq);
            u_s[kq + 0][row] = v.x; u_s[kq + 1][row] = v.y;
            u_s[kq + 2][row] = v.z; u_s[kq + 3][row] = v.w;
        }
#pragma unroll
        for (int i = 0; i < 2; i++) {
            int slot = tid + i * 256;
            int row = slot >> 4, c4 = (slot & 15) << 2;
            *(float4*)&w_s[row][c4] =
                *(const float4*)(w + (size_t)(k0 + kt + row) * DIP_ + DI_ + CDIM_ + c4);
        }
        __syncthreads();
#pragma unroll 8
        for (int k = 0; k < 32; k++) {
            float a[8], b[4];
            *(float4*)&a[0] = *(float4*)&u_s[k][ti * 8];
            *(float4*)&a[4] = *(float4*)&u_s[k][ti * 8 + 4];
            *(float4*)&b[0] = *(float4*)&w_s[k][ni * 4];
#pragma unroll
            for (int q = 0; q < 8; q++)
#pragma unroll
                for (int r = 0; r < 4; r++) acc[q][r] += a[q] * b[r];
        }
    }
    float* dst = g_dtp + ((size_t)blockIdx.y * (B_ * L_) + m0 + ti * 8) * NH_ + ni * 4;
#pragma unroll
    for (int q = 0; q < 8; q++)
        *(float4*)(dst + (size_t)q * NH_) = *(float4*)&acc[q][0];
}

__global__ void dtr_kernel(const float* __restrict__ dt_bias) {
    int i4 = (blockIdx.x * 256 + threadIdx.x) * 4;
    const int TOT = B_ * L_ * NH_;
    float4 x = *(const float4*)(dt_bias + (i4 & (NH_ - 1)));
#pragma unroll
    for (int s = 0; s < KSPL; s++) {
        float4 p = *(const float4*)(g_dtp + (size_t)s * TOT + i4);
        x.x += p.x; x.y += p.y; x.z += p.z; x.w += p.w;
    }
    float4 o;
    o.x = (x.x > 20.f) ? x.x : log1pf(expf(x.x));
    o.y = (x.y > 20.f) ? x.y : log1pf(expf(x.y));
    o.z = (x.z > 20.f) ? x.z : log1pf(expf(x.z));
    o.w = (x.w > 20.f) ? x.w : log1pf(expf(x.w));
    *(float4*)(g_dtv + i4) = o;
}

// ---------------- K2: conv + silu ----------------
__global__ void conv_kernel(const float* __restrict__ conv_w, const float* __restrict__ conv_b) {
    int idx = blockIdx.x * 256 + threadIdx.x;
    int c4 = (idx % (CDIM_ / 4)) * 4;
    int bl = idx / (CDIM_ / 4);
    int l = bl % L_;
    float4 acc = *(const float4*)(conv_b + c4);
    float4 w0 = *(const float4*)(conv_w + (c4 + 0) * DCV);
    float4 w1 = *(const float4*)(conv_w + (c4 + 1) * DCV);
    float4 w2 = *(const float4*)(conv_w + (c4 + 2) * DCV);
    float4 w3 = *(const float4*)(conv_w + (c4 + 3) * DCV);
#pragma unroll
    for (int k = 0; k < DCV; k++) {
        int ls = l + k - (DCV - 1);
        if (ls >= 0) {
            float4 v = *(const float4*)(g_zx + (size_t)(bl - l + ls) * DIP_ + DI_ + c4);
            acc.x += v.x * (&w0.x)[k]; acc.y += v.y * (&w1.x)[k];
            acc.z += v.z * (&w2.x)[k]; acc.w += v.w * (&w3.x)[k];
        }
    }
    acc.x = acc.x / (1.f + __expf(-acc.x));
    acc.y = acc.y / (1.f + __expf(-acc.y));
    acc.z = acc.z / (1.f + __expf(-acc.z));
    acc.w = acc.w / (1.f + __expf(-acc.w));
    *(float4*)(g_xBC + (size_t)bl * CDIM_ + c4) = acc;
}

// ---------------- K4: cumsum ----------------
__global__ void acs_kernel(const float* __restrict__ A_log) {
    int blk = blockIdx.x;
    int h = blk % NH_;
    int bc = blk / NH_;
    int c = bc % NC_;
    int b = bc / NC_;
    int t = threadIdx.x;
    __shared__ float s[CH_];
    float A = -__expf(A_log[h]);
    s[t] = g_dtv[(size_t)(b * L_ + c * CH_ + t) * NH_ + h] * A;
    __syncthreads();
    for (int off = 1; off < CH_; off <<= 1) {
        float v = (t >= off) ? s[t - off] : 0.f;
        __syncthreads();
        s[t] += v;
        __syncthreads();
    }
    g_Acs[(size_t)blk * CH_ + t] = s[t];
}

// ---------------- K5: CB via tf32 mma (proven) ----------------
__global__ __launch_bounds__(256, 1) void cb_kernel() {
    extern __shared__ float cbs[];
    float* C_s = cbs;
    float* B_s = cbs + 64 * 132;
    int z = blockIdx.z;
    int b = z / NC_, c = z % NC_;
    int t0 = blockIdx.y * 64, s0 = blockIdx.x * 64;
    int tid = threadIdx.x;
    int wid = tid >> 5, lane = tid & 31;
    int wm = wid >> 2, wn = wid & 3;
    int grp = lane >> 2, tig = lane & 3;
    const float* xbase = g_xBC + (size_t)(b * L_ + c * CH_) * CDIM_;

#pragma unroll
    for (int i = 0; i < 8; i++) {
        int slot = tid + i * 256;
        int row = slot >> 5, c4 = (slot & 31) << 2;
        float4 cv = *(const float4*)(xbase + (size_t)(t0 + row) * CDIM_ + DI_ + DS_ + c4);
        float4 bv = *(const float4*)(xbase + (size_t)(s0 + row) * CDIM_ + DI_ + c4);
        float4 co, bo;
        co.x = f2tf32f(cv.x); co.y = f2tf32f(cv.y); co.z = f2tf32f(cv.z); co.w = f2tf32f(cv.w);
        bo.x = f2tf32f(bv.x); bo.y = f2tf32f(bv.y); bo.z = f2tf32f(bv.z); bo.w = f2tf32f(bv.w);
        *(float4*)&C_s[row * 132 + c4] = co;
        *(float4*)&B_s[row * 132 + c4] = bo;
    }
    __syncthreads();

    float acc[2][2][4];
#pragma unroll
    for (int mt = 0; mt < 2; mt++)
#pragma unroll
        for (int nt = 0; nt < 2; nt++)
#pragma unroll
            for (int i = 0; i < 4; i++) acc[mt][nt][i] = 0.f;

#pragma unroll
    for (int ks = 0; ks < 16; ks++) {
        uint32_t a[2][4], bf[2][2];
#pragma unroll
        for (int mt = 0; mt < 2; mt++) {
            int r0 = wm * 32 + mt * 16 + grp;
            a[mt][0] = __float_as_uint(C_s[r0 * 132 + ks * 8 + tig]);
            a[mt][1] = __float_as_uint(C_s[(r0 + 8) * 132 + ks * 8 + tig]);
            a[mt][2] = __float_as_uint(C_s[r0 * 132 + ks * 8 + tig + 4]);
            a[mt][3] = __float_as_uint(C_s[(r0 + 8) * 132 + ks * 8 + tig + 4]);
        }
#pragma unroll
        for (int nt = 0; nt < 2; nt++) {
            int cc = wn * 16 + nt * 8 + grp;
            bf[nt][0] = __float_as_uint(B_s[cc * 132 + ks * 8 + tig]);
            bf[nt][1] = __float_as_uint(B_s[cc * 132 + ks * 8 + tig + 4]);
        }
#pragma unroll
        for (int mt = 0; mt < 2; mt++)
#pragma unroll
            for (int nt = 0; nt < 2; nt++)
                MMA_TF32(acc[mt][nt], a[mt][0], a[mt][1], a[mt][2], a[mt][3],
                         bf[nt][0], bf[nt][1]);
    }

#pragma unroll
    for (int mt = 0; mt < 2; mt++)
#pragma unroll
        for (int nt = 0; nt < 2; nt++) {
            int r = t0 + wm * 32 + mt * 16 + grp;
            int col = s0 + wn * 16 + nt * 8 + tig * 2;
            float2 v0, v1;
            v0.x = acc[mt][nt][0]; v0.y = acc[mt][nt][1];
            v1.x = acc[mt][nt][2]; v1.y = acc[mt][nt][3];
            *(float2*)&g_CB[((size_t)z * CH_ + r) * CH_ + col]     = v0;
            *(float2*)&g_CB[((size_t)z * CH_ + r + 8) * CH_ + col] = v1;
        }
}

// ---------------- K6: chunk states via tf32 mma (proven) ----------------
__global__ __launch_bounds__(256) void state_kernel() {
    __shared__ float wx_s[32][72];
    __shared__ float Bt_s[32][136];
    __shared__ float wv[32];
    int bid = blockIdx.x;
    int h = bid % NH_;
    int bc = bid / NH_;
    int c = bc % NC_;
    int b = bc / NC_;
    int tid = threadIdx.x;
    int wid = tid >> 5, lane = tid & 31;
    int wm = wid >> 2, wn = wid & 3;
    int grp = lane >> 2, tig = lane & 3;
    const float* xbc = g_xBC + (size_t)(b * L_ + c * CH_) * CDIM_;
    int ab = ((b * NC_ + c) * NH_ + h) * CH_;
    float acsLast = g_Acs[(size_t)ab + CH_ - 1];

    float acc[2][4][4];
#pragma unroll
    for (int mt = 0; mt < 2; mt++)
#pragma unroll
        for (int nt = 0; nt < 4; nt++)
#pragma unroll
            for (int i = 0; i < 4; i++) acc[mt][nt][i] = 0.f;

    for (int kt = 0; kt < CH_; kt += 32) {
        __syncthreads();
        if (tid < 32) {
            int r = kt + tid;
            wv[tid] = __expf(acsLast - g_Acs[(size_t)ab + r]) *
                      g_dtv[(size_t)(b * L_ + c * CH_ + r) * NH_ + h];
        }
        __syncthreads();
#pragma unroll
        for (int i = 0; i < 2; i++) {
            int slot = tid + i * 256;
            int row = slot >> 4, p4 = (slot & 15) << 2;
            float4 v = *(const float4*)(xbc + (size_t)(kt + row) * CDIM_ + h * HD_ + p4);
            float wgt = wv[row];
            float4 o;
            o.x = f2tf32f(v.x * wgt); o.y = f2tf32f(v.y * wgt);
            o.z = f2tf32f(v.z * wgt); o.w = f2tf32f(v.w * wgt);
            *(float4*)&wx_s[row][p4] = o;
        }
#pragma unroll
        for (int i = 0; i < 4; i++) {
            int slot = tid + i * 256;
            int row = slot >> 5, n4 = (slot & 31) << 2;
            float4 v = *(const float4*)(xbc + (size_t)(kt + row) * CDIM_ + DI_ + n4);
            float4 o;
            o.x = f2tf32f(v.x); o.y = f2tf32f(v.y);
            o.z = f2tf32f(v.z); o.w = f2tf32f(v.w);
            *(float4*)&Bt_s[row][n4] = o;
        }
        __syncthreads();
#pragma unroll
        for (int ks = 0; ks < 4; ks++) {
            uint32_t a[2][4], bf[4][2];
#pragma unroll
            for (int mt = 0; mt < 2; mt++) {
                int r0 = wm * 32 + mt * 16 + grp;
                a[mt][0] = __float_as_uint(wx_s[ks * 8 + tig][r0]);
                a[mt][1] = __float_as_uint(wx_s[ks * 8 + tig][r0 + 8]);
                a[mt][2] = __float_as_uint(wx_s[ks * 8 + tig + 4][r0]);
                a[mt][3] = __float_as_uint(wx_s[ks * 8 + tig + 4][r0 + 8]);
            }
#pragma unroll
            for (int nt = 0; nt < 4; nt++) {
                int cc = wn * 32 + nt * 8 + grp;
                bf[nt][0] = __float_as_uint(Bt_s[ks * 8 + tig][cc]);
                bf[nt][1] = __float_as_uint(Bt_s[ks * 8 + tig + 4][cc]);
            }
#pragma unroll
            for (int mt = 0; mt < 2; mt++)
#pragma unroll
                for (int nt = 0; nt < 4; nt++)
                    MMA_TF32(acc[mt][nt], a[mt][0], a[mt][1], a[mt][2], a[mt][3],
                             bf[nt][0], bf[nt][1]);
        }
    }
    size_t base = (size_t)bid * HD_ * DS_;
#pragma unroll
    for (int mt = 0; mt < 2; mt++)
#pragma unroll
        for (int nt = 0; nt < 4; nt++) {
            int p = wm * 32 + mt * 16 + grp;
            int n = wn * 32 + nt * 8 + tig * 2;
            float2 v0, v1;
            v0.x = acc[mt][nt][0]; v0.y = acc[mt][nt][1];
            v1.x = acc[mt][nt][2]; v1.y = acc[mt][nt][3];
            *(float2*)&g_st[base + (size_t)p * DS_ + n]       = v0;
            *(float2*)&g_st[base + (size_t)(p + 8) * DS_ + n] = v1;
        }
}

// ---------------- K7: recurrence (split 2x) ----------------
__global__ void rec_kernel() {
    int bid = blockIdx.x;
    int half = bid & 1;
    int bh = bid >> 1;
    int h = bh % NH_;
    int b = bh / NH_;
    int tid = threadIdx.x;
    float S[16];
#pragma unroll
    for (int k = 0; k < 16; k++) S[k] = 0.f;
    for (int c = 0; c < NC_; c++) {
        int blk = (b * NC_ + c) * NH_ + h;
        size_t base = (size_t)blk * HD_ * DS_ + (size_t)half * 16 * 256;
        float ef = __expf(g_Acs[(size_t)blk * CH_ + CH_ - 1]);
#pragma unroll
        for (int k = 0; k < 16; k++) {
            size_t e = base + (size_t)k * 256 + tid;
            g_is[e] = S[k];
            S[k] = S[k] * ef + g_st[e];
        }
    }
}

// ---------------- K8: fused Y via tf32 mma (proven) ----------------
__global__ __launch_bounds__(256, 1) void y_kernel(const float* __restrict__ D_skip) {
    extern __shared__ float sm[];
    float* w_s   = sm;
    float* x_s   = w_s + 256 * 68;
    float* st_s  = x_s + 256 * 72;
    float* acs_s = st_s + 128 * 72;
    float* dtv_s = acs_s + 256;
    float* einv_s = dtv_s + 256;

    int bid = blockIdx.x;
    int h = bid % NH_;
    int bch = bid / NH_;
    int ch = bch % NC_;
    int b = bch / NC_;
    int tid = threadIdx.x;
    int wid = tid >> 5, lane = tid & 31;
    int wm = wid >> 1, wn = wid & 1;
    int grp = lane >> 2, tig = lane & 3;
    int t = tid;

    const float* xbc = g_xBC + (size_t)(b * L_ + ch * CH_) * CDIM_;
    const float* cbrow = g_CB + ((size_t)(b * NC_ + ch) * CH_ + t) * CH_;
    const float* isb = g_is + (size_t)bid * HD_ * DS_;
    int ab = bid * CH_;

    for (int slot = tid; slot < 4096; slot += 256) {
        int row = slot >> 4, p4 = (slot & 15) << 2;
        float4 v = *(const float4*)(xbc + (size_t)row * CDIM_ + h * HD_ + p4);
        float4 o;
        o.x = f2tf32f(v.x); o.y = f2tf32f(v.y);
        o.z = f2tf32f(v.z); o.w = f2tf32f(v.w);
        *(float4*)&x_s[row * 72 + p4] = o;
    }
    for (int slot = tid; slot < 2048; slot += 256) {
        int p = slot & 63, ng = (slot >> 6) << 2;
        float4 v = *(const float4*)(isb + (size_t)p * DS_ + ng);
        st_s[(ng + 0) * 72 + p] = f2tf32f(v.x);
        st_s[(ng + 1) * 72 + p] = f2tf32f(v.y);
        st_s[(ng + 2) * 72 + p] = f2tf32f(v.z);
        st_s[(ng + 3) * 72 + p] = f2tf32f(v.w);
    }
    acs_s[tid] = g_Acs[(size_t)ab + tid];
    dtv_s[tid] = g_dtv[(size_t)(b * L_ + ch * CH_ + tid) * NH_ + h];

    float acc[4][4][4];
#pragma unroll
    for (int mt = 0; mt < 4; mt++)
#pragma unroll
        for (int nt = 0; nt < 4; nt++)
#pragma unroll
            for (int i = 0; i < 4; i++) acc[mt][nt][i] = 0.f;

    for (int k0 = 0; k0 < CH_; k0 += 64) {
        __syncthreads();
        if (tid < 64) {
            int sb = k0 + (tid & 0x30);
            einv_s[tid] = __expf(fminf(acs_s[sb] - acs_s[k0 + tid], 80.f));
        }
        __syncthreads();
#pragma unroll
        for (int sub = 0; sub < 4; sub++) {
            int sbase = k0 + sub * 16;
            if (t >= sbase) {
                float et = __expf(acs_s[t] - acs_s[sbase]);
#pragma unroll
                for (int jj = 0; jj < 16; jj += 4) {
                    float4 cb4 = *(const float4*)(cbrow + sbase + jj);
                    int s0q = sbase + jj;
                    float4 o;
                    o.x = (s0q + 0 <= t) ? f2tf32f(et * einv_s[sub * 16 + jj + 0] * cb4.x * dtv_s[s0q + 0]) : 0.f;
                    o.y = (s0q + 1 <= t) ? f2tf32f(et * einv_s[sub * 16 + jj + 1] * cb4.y * dtv_s[s0q + 1]) : 0.f;
                    o.z = (s0q + 2 <= t) ? f2tf32f(et * einv_s[sub * 16 + jj + 2] * cb4.z * dtv_s[s0q + 2]) : 0.f;
                    o.w = (s0q + 3 <= t) ? f2tf32f(et * einv_s[sub * 16 + jj + 3] * cb4.w * dtv_s[s0q + 3]) : 0.f;
                    *(float4*)&w_s[t * 68 + sub * 16 + jj] = o;
                }
            } else {
                float4 z4 = {0.f, 0.f, 0.f, 0.f};
#pragma unroll
                for (int jj = 0; jj < 16; jj += 4)
                    *(float4*)&w_s[t * 68 + sub * 16 + jj] = z4;
            }
        }
        __syncthreads();
        if (wm * 64 + 63 >= k0) {
#pragma unroll
            for (int ks = 0; ks < 8; ks++) {
                uint32_t a[4][4], bfr[4][2];
#pragma unroll
                for (int mt = 0; mt < 4; mt++) {
                    int r0 = wm * 64 + mt * 16 + grp;
                    a[mt][0] = __float_as_uint(w_s[r0 * 68 + ks * 8 + tig]);
                    a[mt][1] = __float_as_uint(w_s[(r0 + 8) * 68 + ks * 8 + tig]);
                    a[mt][2] = __float_as_uint(w_s[r0 * 68 + ks * 8 + tig + 4]);
                    a[mt][3] = __float_as_uint(w_s[(r0 + 8) * 68 + ks * 8 + tig + 4]);
                }
#pragma unroll
                for (int nt = 0; nt < 4; nt++) {
                    int cc = wn * 32 + nt * 8 + grp;
                    bfr[nt][0] = __float_as_uint(x_s[(k0 + ks * 8 + tig) * 72 + cc]);
                    bfr[nt][1] = __float_as_uint(x_s[(k0 + ks * 8 + tig + 4) * 72 + cc]);
                }
#pragma unroll
                for (int mt = 0; mt < 4; mt++)
#pragma unroll
                    for (int nt = 0; nt < 4; nt++)
                        MMA_TF32(acc[mt][nt], a[mt][0], a[mt][1], a[mt][2], a[mt][3],
                                 bfr[nt][0], bfr[nt][1]);
            }
        }
    }

    float et0 = __expf(acs_s[t]);
    for (int n0 = 0; n0 < DS_; n0 += 64) {
        __syncthreads();
#pragma unroll
        for (int j = 0; j < 64; j += 4) {
            float4 c4 = *(const float4*)(xbc + (size_t)t * CDIM_ + DI_ + DS_ + n0 + j);
            float4 o;
            o.x = f2tf32f(c4.x * et0); o.y = f2tf32f(c4.y * et0);
            o.z = f2tf32f(c4.z * et0); o.w = f2tf32f(c4.w * et0);
            *(float4*)&w_s[t * 68 + j] = o;
        }
        __syncthreads();
#pragma unroll
        for (int ks = 0; ks < 8; ks++) {
            uint32_t a[4][4], bfr[4][2];
#pragma unroll
            for (int mt = 0; mt < 4; mt++) {
                int r0 = wm * 64 + mt * 16 + grp;
                a[mt][0] = __float_as_uint(w_s[r0 * 68 + ks * 8 + tig]);
                a[mt][1] = __float_as_uint(w_s[(r0 + 8) * 68 + ks * 8 + tig]);
                a[mt][2] = __float_as_uint(w_s[r0 * 68 + ks * 8 + tig + 4]);
                a[mt][3] = __float_as_uint(w_s[(r0 + 8) * 68 + ks * 8 + tig + 4]);
            }
#pragma unroll
            for (int nt = 0; nt < 4; nt++) {
                int cc = wn * 32 + nt * 8 + grp;
                bfr[nt][0] = __float_as_uint(st_s[(n0 + ks * 8 + tig) * 72 + cc]);
                bfr[nt][1] = __float_as_uint(st_s[(n0 + ks * 8 + tig + 4) * 72 + cc]);
            }
#pragma unroll
            for (int mt = 0; mt < 4; mt++)
#pragma unroll
                for (int nt = 0; nt < 4; nt++)
                    MMA_TF32(acc[mt][nt], a[mt][0], a[mt][1], a[mt][2], a[mt][3],
                             bfr[nt][0], bfr[nt][1]);
        }
    }

    float dsk = D_skip[h];
    size_t rowbase = (size_t)(b * L_ + ch * CH_);
#pragma unroll
    for (int mt = 0; mt < 4; mt++)
#pragma unroll
        for (int nt = 0; nt < 4; nt++) {
            int r0 = wm * 64 + mt * 16 + grp;
            int cc = wn * 32 + nt * 8 + tig * 2;
            float2 v0, v1;
            v0.x = acc[mt][nt][0] + dsk * x_s[r0 * 72 + cc];
            v0.y = acc[mt][nt][1] + dsk * x_s[r0 * 72 + cc + 1];
            v1.x = acc[mt][nt][2] + dsk * x_s[(r0 + 8) * 72 + cc];
            v1.y = acc[mt][nt][3] + dsk * x_s[(r0 + 8) * 72 + cc + 1];
            *(float2*)&g_y[(rowbase + r0) * DI_ + h * HD_ + cc]       = v0;
            *(float2*)&g_y[(rowbase + r0 + 8) * DI_ + h * HD_ + cc]   = v1;
        }
}

// ---------------- K9: gate + RMSNorm ----------------
__global__ void gate_kernel(const float* __restrict__ norm_w, float* __restrict__ out) {
    int row = blockIdx.x;
    int tid = threadIdx.x;
    int lane = tid & 31, wid = tid >> 5;
    __shared__ float yg_s[DI_];
    __shared__ float wsum[8];
    float ss = 0.f;
#pragma unroll
    for (int it = 0; it < DI_ / 1024; it++) {
        int i = it * 1024 + tid * 4;
        float4 yv = *(const float4*)(g_y + (size_t)row * DI_ + i);
        float4 z  = *(const float4*)(g_zx + (size_t)row * DIP_ + i);
        float4 yg;
        yg.x = yv.x * (z.x / (1.f + __expf(-z.x)));
        yg.y = yv.y * (z.y / (1.f + __expf(-z.y)));
        yg.z = yv.z * (z.z / (1.f + __expf(-z.z)));
        yg.w = yv.w * (z.w / (1.f + __expf(-z.w)));
        *(float4*)&yg_s[i] = yg;
        ss += yg.x * yg.x + yg.y * yg.y + yg.z * yg.z + yg.w * yg.w;
    }
#pragma unroll
    for (int off = 16; off > 0; off >>= 1)
        ss += __shfl_xor_sync(0xffffffffu, ss, off);
    if (lane == 0) wsum[wid] = ss;
    __syncthreads();
    float tot = wsum[0] + wsum[1] + wsum[2] + wsum[3]
              + wsum[4] + wsum[5] + wsum[6] + wsum[7];
    float r = rsqrtf(tot / (float)DI_ + 1e-5f);
#pragma unroll
    for (int it = 0; it < DI_ / 1024; it++) {
        int i = it * 1024 + tid * 4;
        float4 yg = *(float4*)&yg_s[i];
        float4 nw = *(const float4*)(norm_w + i);
        float4 o;
        o.x = yg.x * r * nw.x; o.y = yg.y * r * nw.y;
        o.z = yg.z * r * nw.z; o.w = yg.w * r * nw.w;
        *(float4*)(out + (size_t)row * DI_ + i) = o;
    }
}

// ---------------- launch ----------------
extern "C" void kernel_launch(void* const* d_in, const int* in_sizes, int n_in,
                              void* d_out, int out_size) {
    const float* u       = (const float*)d_in[0];
    const float* w_in    = (const float*)d_in[1];
    const float* conv_w  = (const float*)d_in[2];
    const float* conv_b  = (const float*)d_in[3];
    const float* dt_bias = (const float*)d_in[4];
    const float* A_log   = (const float*)d_in[5];
    const float* D_skip  = (const float*)d_in[6];
    const float* norm_w  = (const float*)d_in[7];
    float* out = (float*)d_out;

    const int Y_SMEM  = (256 * 68 + 256 * 72 + 128 * 72 + 256 + 256 + 64) * 4;
    const int CB_SMEM = 2 * 64 * 132 * 4;
    cudaFuncSetAttribute(y_kernel, cudaFuncAttributeMaxDynamicSharedMemorySize, Y_SMEM);
    cudaFuncSetAttribute(cb_kernel, cudaFuncAttributeMaxDynamicSharedMemorySize, CB_SMEM);
    cudaFuncSetAttribute(gemm_tf32_kernel, cudaFuncAttributeMaxDynamicSharedMemorySize, 3 * STG_);

    gemm_tf32_kernel<<<dim3(GN_ / 256, (B_ * L_) / 128), 256, 3 * STG_>>>(u, w_in);
    dtg_part_kernel<<<dim3((B_ * L_) / 128, KSPL), 256>>>(u, w_in);
    dtr_kernel<<<(B_ * L_ * NH_) / 4 / 256, 256>>>(dt_bias);
    conv_kernel<<<(B_ * L_ * CDIM_) / 4 / 256, 256>>>(conv_w, conv_b);
    acs_kernel<<<B_ * NC_ * NH_, CH_>>>(A_log);
    cb_kernel<<<dim3(4, 4, B_ * NC_), 256, CB_SMEM>>>();
    state_kernel<<<B_ * NC_ * NH_, 256>>>();
    rec_kernel<<<B_ * NH_ * 2, 256>>>();
    y_kernel<<<B_ * NC_ * NH_, 256, Y_SMEM>>>(D_skip);
    gate_kernel<<<B_ * L_, 256>>>(norm_w, out);
}

// round 16
// speedup vs baseline: 1.0855x; 1.0855x over previous
#include <cuda_runtime.h>
#include <cstdint>
#include <cmath>

#define B_    2
#define L_    2048
#define DM_   2048
#define DIP_  8512
#define DI_   4096
#define CDIM_ 4352
#define NH_   64
#define HD_   64
#define DS_   128
#define CH_   256
#define NC_   8
#define DCV   4
#define GN_   8448
#define KSPL  32

// ---------------- scratch ----------------
__device__ float g_zx  [(size_t)B_*L_*DIP_];
__device__ float g_xBC [(size_t)B_*L_*CDIM_];
__device__ float g_dtv [(size_t)B_*L_*NH_];
__device__ float g_dtp [(size_t)KSPL*B_*L_*NH_];
__device__ float g_Acs [(size_t)B_*NC_*NH_*CH_];
__device__ float g_CB  [(size_t)B_*NC_*CH_*CH_];
__device__ float g_st  [(size_t)B_*NC_*NH_*HD_*DS_];
__device__ float g_is  [(size_t)B_*NC_*NH_*HD_*DS_];
__device__ float g_y   [(size_t)B_*L_*DI_];
__device__ __align__(16) float g_ut[(size_t)B_*L_*DM_];
__device__ __align__(16) float g_wt[(size_t)DM_*GN_];

__device__ __forceinline__ float f2tf32f(float x) {
    uint32_t r;
    asm("cvt.rna.tf32.f32 %0, %1;" : "=r"(r) : "f"(x));
    return __uint_as_float(r);
}
__device__ __forceinline__ uint32_t smem_u32(const void* p) {
    uint32_t a;
    asm("{ .reg .u64 t; cvta.to.shared.u64 t, %1; cvt.u32.u64 %0, t; }" : "=r"(a) : "l"(p));
    return a;
}
__device__ __forceinline__ void cpa16(uint32_t dst, const void* src) {
    asm volatile("cp.async.cg.shared.global [%0], [%1], 16;" :: "r"(dst), "l"(src));
}
#define CPA_COMMIT() asm volatile("cp.async.commit_group;" ::: "memory")
#define CPA_WAIT1()  asm volatile("cp.async.wait_group 1;" ::: "memory")
#define MMA_TF32(acc, a0,a1,a2,a3, b0,b1)                                      \
    asm volatile("mma.sync.aligned.m16n8k8.row.col.f32.tf32.tf32.f32 "         \
        "{%0,%1,%2,%3}, {%4,%5,%6,%7}, {%8,%9}, {%0,%1,%2,%3};"                \
        : "+f"((acc)[0]), "+f"((acc)[1]), "+f"((acc)[2]), "+f"((acc)[3])       \
        : "r"(a0), "r"(a1), "r"(a2), "r"(a3), "r"(b0), "r"(b1))

// ---------------- K0a/K0b: tf32 pre-round (restored R14) ----------------
__global__ void uconv_kernel(const float* __restrict__ u) {
    size_t i = (size_t)blockIdx.x * 256 + threadIdx.x;
    float4 v = ((const float4*)u)[i];
    v.x = f2tf32f(v.x); v.y = f2tf32f(v.y);
    v.z = f2tf32f(v.z); v.w = f2tf32f(v.w);
    ((float4*)g_ut)[i] = v;
}
__global__ void wconv_kernel(const float* __restrict__ w) {
    size_t i = (size_t)blockIdx.x * 256 + threadIdx.x;
    int row = (int)(i / (GN_ / 4));
    int c4  = (int)(i % (GN_ / 4)) * 4;
    float4 v = *(const float4*)(w + (size_t)row * DIP_ + c4);
    v.x = f2tf32f(v.x); v.y = f2tf32f(v.y);
    v.z = f2tf32f(v.z); v.w = f2tf32f(v.w);
    *(float4*)(g_wt + (size_t)row * GN_ + c4) = v;
}

// ---------------- K1: main tf32 GEMM, 3-stage cp.async (R14 proven best) ------
#define ASTG 18432
#define BSTG 33792
#define STG_ (ASTG + BSTG)
__global__ __launch_bounds__(256, 1) void gemm_tf32_kernel() {
    extern __shared__ char sal[];
    const int tid = threadIdx.x;
    const int m0 = blockIdx.y * 128;
    const int n0 = blockIdx.x * 256;
    const int lane = tid & 31, wid = tid >> 5;
    const int wm = wid >> 2, wn = wid & 3;
    const int grp = lane >> 2, tig = lane & 3;
    const uint32_t sbase = smem_u32(sal);
    const int NKT = DM_ / 32;

    float acc[4][8][4];
#pragma unroll
    for (int mt = 0; mt < 4; mt++)
#pragma unroll
        for (int nt = 0; nt < 8; nt++)
#pragma unroll
            for (int i = 0; i < 4; i++) acc[mt][nt][i] = 0.f;

    auto issue = [&](int buf, int kt) {
        uint32_t ab = sbase + buf * STG_;
        uint32_t bb = ab + ASTG;
#pragma unroll
        for (int i = 0; i < 4; i++) {
            int slot = tid + i * 256;
            int row = slot >> 3, c = slot & 7;
            cpa16(ab + row * 144 + c * 16,
                  g_ut + (size_t)(m0 + row) * DM_ + kt * 32 + c * 4);
        }
#pragma unroll
        for (int i = 0; i < 8; i++) {
            int slot = tid + i * 256;
            int row = slot >> 6, c = slot & 63;
            cpa16(bb + row * 1056 + c * 16,
                  g_wt + (size_t)(kt * 32 + row) * GN_ + n0 + c * 4);
        }
    };

    issue(0, 0); CPA_COMMIT();
    issue(1, 1); CPA_COMMIT();

    for (int kt = 0; kt < NKT; kt++) {
        CPA_WAIT1();
        __syncthreads();
        if (kt + 2 < NKT) issue((kt + 2) % 3, kt + 2);
        CPA_COMMIT();

        const float* As = (const float*)(sal + (kt % 3) * STG_);
        const float* Bs = (const float*)(sal + (kt % 3) * STG_ + ASTG);
#pragma unroll
        for (int ks = 0; ks < 4; ks++) {
            uint32_t a[4][4], b[8][2];
#pragma unroll
            for (int mt = 0; mt < 4; mt++) {
                int r0 = wm * 64 + mt * 16 + grp;
                a[mt][0] = __float_as_uint(As[r0 * 36 + ks * 8 + tig]);
                a[mt][1] = __float_as_uint(As[(r0 + 8) * 36 + ks * 8 + tig]);
                a[mt][2] = __float_as_uint(As[r0 * 36 + ks * 8 + tig + 4]);
                a[mt][3] = __float_as_uint(As[(r0 + 8) * 36 + ks * 8 + tig + 4]);
            }
#pragma unroll
            for (int nt = 0; nt < 8; nt++) {
                int cc = wn * 64 + nt * 8 + grp;
                b[nt][0] = __float_as_uint(Bs[(ks * 8 + tig) * 264 + cc]);
                b[nt][1] = __float_as_uint(Bs[(ks * 8 + tig + 4) * 264 + cc]);
            }
#pragma unroll
            for (int mt = 0; mt < 4; mt++)
#pragma unroll
                for (int nt = 0; nt < 8; nt++)
                    MMA_TF32(acc[mt][nt], a[mt][0], a[mt][1], a[mt][2], a[mt][3],
                             b[nt][0], b[nt][1]);
        }
        __syncthreads();
    }

#pragma unroll
    for (int mt = 0; mt < 4; mt++)
#pragma unroll
        for (int nt = 0; nt < 8; nt++) {
            int row = m0 + wm * 64 + mt * 16 + grp;
            int col = n0 + wn * 64 + nt * 8 + tig * 2;
            float2 v0, v1;
            v0.x = acc[mt][nt][0]; v0.y = acc[mt][nt][1];
            v1.x = acc[mt][nt][2]; v1.y = acc[mt][nt][3];
            *(float2*)&g_zx[(size_t)row * DIP_ + col]       = v0;
            *(float2*)&g_zx[(size_t)(row + 8) * DIP_ + col] = v1;
        }
}

// ---------------- K1b: dt GEMM K-split (KSPL=32, proven) ----------------
__global__ __launch_bounds__(256) void dtg_part_kernel(const float* __restrict__ u,
                                                       const float* __restrict__ w) {
    __shared__ float u_s[32][136];
    __shared__ float w_s[32][68];
    const int m0 = blockIdx.x * 128;
    const int k0 = blockIdx.y * 64;
    const int tid = threadIdx.x;
    const int ti = tid >> 4, ni = tid & 15;
    float acc[8][4];
#pragma unroll
    for (int i = 0; i < 8; i++)
#pragma unroll
        for (int j = 0; j < 4; j++) acc[i][j] = 0.f;

    for (int kt = 0; kt < 64; kt += 32) {
        __syncthreads();
#pragma unroll
        for (int i = 0; i < 4; i++) {
            int slot = tid + i * 256;
            int row = slot >> 3, kq = (slot & 7) << 2;
            float4 v = *(const float4*)(u + (size_t)(m0 + row) * DM_ + k0 + kt + kq);
            u_s[kq + 0][row] = v.x; u_s[kq + 1][row] = v.y;
            u_s[kq + 2][row] = v.z; u_s[kq + 3][row] = v.w;
        }
#pragma unroll
        for (int i = 0; i < 2; i++) {
            int slot = tid + i * 256;
            int row = slot >> 4, c4 = (slot & 15) << 2;
            *(float4*)&w_s[row][c4] =
                *(const float4*)(w + (size_t)(k0 + kt + row) * DIP_ + DI_ + CDIM_ + c4);
        }
        __syncthreads();
#pragma unroll 8
        for (int k = 0; k < 32; k++) {
            float a[8], b[4];
            *(float4*)&a[0] = *(float4*)&u_s[k][ti * 8];
            *(float4*)&a[4] = *(float4*)&u_s[k][ti * 8 + 4];
            *(float4*)&b[0] = *(float4*)&w_s[k][ni * 4];
#pragma unroll
            for (int q = 0; q < 8; q++)
#pragma unroll
                for (int r = 0; r < 4; r++) acc[q][r] += a[q] * b[r];
        }
    }
    float* dst = g_dtp + ((size_t)blockIdx.y * (B_ * L_) + m0 + ti * 8) * NH_ + ni * 4;
#pragma unroll
    for (int q = 0; q < 8; q++)
        *(float4*)(dst + (size_t)q * NH_) = *(float4*)&acc[q][0];
}

__global__ void dtr_kernel(const float* __restrict__ dt_bias) {
    int i4 = (blockIdx.x * 256 + threadIdx.x) * 4;
    const int TOT = B_ * L_ * NH_;
    float4 x = *(const float4*)(dt_bias + (i4 & (NH_ - 1)));
#pragma unroll
    for (int s = 0; s < KSPL; s++) {
        float4 p = *(const float4*)(g_dtp + (size_t)s * TOT + i4);
        x.x += p.x; x.y += p.y; x.z += p.z; x.w += p.w;
    }
    float4 o;
    o.x = (x.x > 20.f) ? x.x : log1pf(expf(x.x));
    o.y = (x.y > 20.f) ? x.y : log1pf(expf(x.y));
    o.z = (x.z > 20.f) ? x.z : log1pf(expf(x.z));
    o.w = (x.w > 20.f) ? x.w : log1pf(expf(x.w));
    *(float4*)(g_dtv + i4) = o;
}

// ---------------- K2: conv + silu, 2 outputs/thread (2.5 loads/output vs 4) ----
__global__ void conv_kernel(const float* __restrict__ conv_w, const float* __restrict__ conv_b) {
    int idx = blockIdx.x * 256 + threadIdx.x;        // over (B*L/2)*(CDIM/4)
    int c4 = (idx % (CDIM_ / 4)) * 4;
    int blp = idx / (CDIM_ / 4);
    int b  = blp / (L_ / 2);
    int l0 = (blp % (L_ / 2)) * 2;                   // even l
    size_t bl0 = (size_t)b * L_ + l0;

    float4 bias = *(const float4*)(conv_b + c4);
    float4 w0 = *(const float4*)(conv_w + (c4 + 0) * DCV);
    float4 w1 = *(const float4*)(conv_w + (c4 + 1) * DCV);
    float4 w2 = *(const float4*)(conv_w + (c4 + 2) * DCV);
    float4 w3 = *(const float4*)(conv_w + (c4 + 3) * DCV);

    // positions l0-3 .. l0+1 (5 loads for 2 outputs)
    float4 v[5];
#pragma unroll
    for (int j = 0; j < 5; j++) {
        int ls = l0 - 3 + j;
        if (ls >= 0)
            v[j] = *(const float4*)(g_zx + (bl0 - 3 + j) * DIP_ + DI_ + c4);
        else
            v[j] = make_float4(0.f, 0.f, 0.f, 0.f);
    }

    float4 a0 = bias, a1 = bias;
#pragma unroll
    for (int k = 0; k < DCV; k++) {
        float wk0 = (&w0.x)[k], wk1 = (&w1.x)[k], wk2 = (&w2.x)[k], wk3 = (&w3.x)[k];
        a0.x += v[k].x * wk0;     a0.y += v[k].y * wk1;
        a0.z += v[k].z * wk2;     a0.w += v[k].w * wk3;
        a1.x += v[k + 1].x * wk0; a1.y += v[k + 1].y * wk1;
        a1.z += v[k + 1].z * wk2; a1.w += v[k + 1].w * wk3;
    }
    a0.x = a0.x / (1.f + __expf(-a0.x));
    a0.y = a0.y / (1.f + __expf(-a0.y));
    a0.z = a0.z / (1.f + __expf(-a0.z));
    a0.w = a0.w / (1.f + __expf(-a0.w));
    a1.x = a1.x / (1.f + __expf(-a1.x));
    a1.y = a1.y / (1.f + __expf(-a1.y));
    a1.z = a1.z / (1.f + __expf(-a1.z));
    a1.w = a1.w / (1.f + __expf(-a1.w));
    *(float4*)(g_xBC + bl0 * CDIM_ + c4)       = a0;
    *(float4*)(g_xBC + (bl0 + 1) * CDIM_ + c4) = a1;
}

// ---------------- K4: cumsum ----------------
__global__ void acs_kernel(const float* __restrict__ A_log) {
    int blk = blockIdx.x;
    int h = blk % NH_;
    int bc = blk / NH_;
    int c = bc % NC_;
    int b = bc / NC_;
    int t = threadIdx.x;
    __shared__ float s[CH_];
    float A = -__expf(A_log[h]);
    s[t] = g_dtv[(size_t)(b * L_ + c * CH_ + t) * NH_ + h] * A;
    __syncthreads();
    for (int off = 1; off < CH_; off <<= 1) {
        float v = (t >= off) ? s[t - off] : 0.f;
        __syncthreads();
        s[t] += v;
        __syncthreads();
    }
    g_Acs[(size_t)blk * CH_ + t] = s[t];
}

// ---------------- K5: CB via tf32 mma (proven) ----------------
__global__ __launch_bounds__(256, 1) void cb_kernel() {
    extern __shared__ float cbs[];
    float* C_s = cbs;
    float* B_s = cbs + 64 * 132;
    int z = blockIdx.z;
    int b = z / NC_, c = z % NC_;
    int t0 = blockIdx.y * 64, s0 = blockIdx.x * 64;
    int tid = threadIdx.x;
    int wid = tid >> 5, lane = tid & 31;
    int wm = wid >> 2, wn = wid & 3;
    int grp = lane >> 2, tig = lane & 3;
    const float* xbase = g_xBC + (size_t)(b * L_ + c * CH_) * CDIM_;

#pragma unroll
    for (int i = 0; i < 8; i++) {
        int slot = tid + i * 256;
        int row = slot >> 5, c4 = (slot & 31) << 2;
        float4 cv = *(const float4*)(xbase + (size_t)(t0 + row) * CDIM_ + DI_ + DS_ + c4);
        float4 bv = *(const float4*)(xbase + (size_t)(s0 + row) * CDIM_ + DI_ + c4);
        float4 co, bo;
        co.x = f2tf32f(cv.x); co.y = f2tf32f(cv.y); co.z = f2tf32f(cv.z); co.w = f2tf32f(cv.w);
        bo.x = f2tf32f(bv.x); bo.y = f2tf32f(bv.y); bo.z = f2tf32f(bv.z); bo.w = f2tf32f(bv.w);
        *(float4*)&C_s[row * 132 + c4] = co;
        *(float4*)&B_s[row * 132 + c4] = bo;
    }
    __syncthreads();

    float acc[2][2][4];
#pragma unroll
    for (int mt = 0; mt < 2; mt++)
#pragma unroll
        for (int nt = 0; nt < 2; nt++)
#pragma unroll
            for (int i = 0; i < 4; i++) acc[mt][nt][i] = 0.f;

#pragma unroll
    for (int ks = 0; ks < 16; ks++) {
        uint32_t a[2][4], bf[2][2];
#pragma unroll
        for (int mt = 0; mt < 2; mt++) {
            int r0 = wm * 32 + mt * 16 + grp;
            a[mt][0] = __float_as_uint(C_s[r0 * 132 + ks * 8 + tig]);
            a[mt][1] = __float_as_uint(C_s[(r0 + 8) * 132 + ks * 8 + tig]);
            a[mt][2] = __float_as_uint(C_s[r0 * 132 + ks * 8 + tig + 4]);
            a[mt][3] = __float_as_uint(C_s[(r0 + 8) * 132 + ks * 8 + tig + 4]);
        }
#pragma unroll
        for (int nt = 0; nt < 2; nt++) {
            int cc = wn * 16 + nt * 8 + grp;
            bf[nt][0] = __float_as_uint(B_s[cc * 132 + ks * 8 + tig]);
            bf[nt][1] = __float_as_uint(B_s[cc * 132 + ks * 8 + tig + 4]);
        }
#pragma unroll
        for (int mt = 0; mt < 2; mt++)
#pragma unroll
            for (int nt = 0; nt < 2; nt++)
                MMA_TF32(acc[mt][nt], a[mt][0], a[mt][1], a[mt][2], a[mt][3],
                         bf[nt][0], bf[nt][1]);
    }

#pragma unroll
    for (int mt = 0; mt < 2; mt++)
#pragma unroll
        for (int nt = 0; nt < 2; nt++) {
            int r = t0 + wm * 32 + mt * 16 + grp;
            int col = s0 + wn * 16 + nt * 8 + tig * 2;
            float2 v0, v1;
            v0.x = acc[mt][nt][0]; v0.y = acc[mt][nt][1];
            v1.x = acc[mt][nt][2]; v1.y = acc[mt][nt][3];
            *(float2*)&g_CB[((size_t)z * CH_ + r) * CH_ + col]     = v0;
            *(float2*)&g_CB[((size_t)z * CH_ + r + 8) * CH_ + col] = v1;
        }
}

// ---------------- K6: chunk states via tf32 mma (proven) ----------------
__global__ __launch_bounds__(256) void state_kernel() {
    __shared__ float wx_s[32][72];
    __shared__ float Bt_s[32][136];
    __shared__ float wv[32];
    int bid = blockIdx.x;
    int h = bid % NH_;
    int bc = bid / NH_;
    int c = bc % NC_;
    int b = bc / NC_;
    int tid = threadIdx.x;
    int wid = tid >> 5, lane = tid & 31;
    int wm = wid >> 2, wn = wid & 3;
    int grp = lane >> 2, tig = lane & 3;
    const float* xbc = g_xBC + (size_t)(b * L_ + c * CH_) * CDIM_;
    int ab = ((b * NC_ + c) * NH_ + h) * CH_;
    float acsLast = g_Acs[(size_t)ab + CH_ - 1];

    float acc[2][4][4];
#pragma unroll
    for (int mt = 0; mt < 2; mt++)
#pragma unroll
        for (int nt = 0; nt < 4; nt++)
#pragma unroll
            for (int i = 0; i < 4; i++) acc[mt][nt][i] = 0.f;

    for (int kt = 0; kt < CH_; kt += 32) {
        __syncthreads();
        if (tid < 32) {
            int r = kt + tid;
            wv[tid] = __expf(acsLast - g_Acs[(size_t)ab + r]) *
                      g_dtv[(size_t)(b * L_ + c * CH_ + r) * NH_ + h];
        }
        __syncthreads();
#pragma unroll
        for (int i = 0; i < 2; i++) {
            int slot = tid + i * 256;
            int row = slot >> 4, p4 = (slot & 15) << 2;
            float4 v = *(const float4*)(xbc + (size_t)(kt + row) * CDIM_ + h * HD_ + p4);
            float wgt = wv[row];
            float4 o;
            o.x = f2tf32f(v.x * wgt); o.y = f2tf32f(v.y * wgt);
            o.z = f2tf32f(v.z * wgt); o.w = f2tf32f(v.w * wgt);
            *(float4*)&wx_s[row][p4] = o;
        }
#pragma unroll
        for (int i = 0; i < 4; i++) {
            int slot = tid + i * 256;
            int row = slot >> 5, n4 = (slot & 31) << 2;
            float4 v = *(const float4*)(xbc + (size_t)(kt + row) * CDIM_ + DI_ + n4);
            float4 o;
            o.x = f2tf32f(v.x); o.y = f2tf32f(v.y);
            o.z = f2tf32f(v.z); o.w = f2tf32f(v.w);
            *(float4*)&Bt_s[row][n4] = o;
        }
        __syncthreads();
#pragma unroll
        for (int ks = 0; ks < 4; ks++) {
            uint32_t a[2][4], bf[4][2];
#pragma unroll
            for (int mt = 0; mt < 2; mt++) {
                int r0 = wm * 32 + mt * 16 + grp;
                a[mt][0] = __float_as_uint(wx_s[ks * 8 + tig][r0]);
                a[mt][1] = __float_as_uint(wx_s[ks * 8 + tig][r0 + 8]);
                a[mt][2] = __float_as_uint(wx_s[ks * 8 + tig + 4][r0]);
                a[mt][3] = __float_as_uint(wx_s[ks * 8 + tig + 4][r0 + 8]);
            }
#pragma unroll
            for (int nt = 0; nt < 4; nt++) {
                int cc = wn * 32 + nt * 8 + grp;
                bf[nt][0] = __float_as_uint(Bt_s[ks * 8 + tig][cc]);
                bf[nt][1] = __float_as_uint(Bt_s[ks * 8 + tig + 4][cc]);
            }
#pragma unroll
            for (int mt = 0; mt < 2; mt++)
#pragma unroll
                for (int nt = 0; nt < 4; nt++)
                    MMA_TF32(acc[mt][nt], a[mt][0], a[mt][1], a[mt][2], a[mt][3],
                             bf[nt][0], bf[nt][1]);
        }
    }
    size_t base = (size_t)bid * HD_ * DS_;
#pragma unroll
    for (int mt = 0; mt < 2; mt++)
#pragma unroll
        for (int nt = 0; nt < 4; nt++) {
            int p = wm * 32 + mt * 16 + grp;
            int n = wn * 32 + nt * 8 + tig * 2;
            float2 v0, v1;
            v0.x = acc[mt][nt][0]; v0.y = acc[mt][nt][1];
            v1.x = acc[mt][nt][2]; v1.y = acc[mt][nt][3];
            *(float2*)&g_st[base + (size_t)p * DS_ + n]       = v0;
            *(float2*)&g_st[base + (size_t)(p + 8) * DS_ + n] = v1;
        }
}

// ---------------- K7: recurrence (split 2x) ----------------
__global__ void rec_kernel() {
    int bid = blockIdx.x;
    int half = bid & 1;
    int bh = bid >> 1;
    int h = bh % NH_;
    int b = bh / NH_;
    int tid = threadIdx.x;
    float S[16];
#pragma unroll
    for (int k = 0; k < 16; k++) S[k] = 0.f;
    for (int c = 0; c < NC_; c++) {
        int blk = (b * NC_ + c) * NH_ + h;
        size_t base = (size_t)blk * HD_ * DS_ + (size_t)half * 16 * 256;
        float ef = __expf(g_Acs[(size_t)blk * CH_ + CH_ - 1]);
#pragma unroll
        for (int k = 0; k < 16; k++) {
            size_t e = base + (size_t)k * 256 + tid;
            g_is[e] = S[k];
            S[k] = S[k] * ef + g_st[e];
        }
    }
}

// ---------------- K8: fused Y via tf32 mma (proven) ----------------
__global__ __launch_bounds__(256, 1) void y_kernel(const float* __restrict__ D_skip) {
    extern __shared__ float sm[];
    float* w_s   = sm;
    float* x_s   = w_s + 256 * 68;
    float* st_s  = x_s + 256 * 72;
    float* acs_s = st_s + 128 * 72;
    float* dtv_s = acs_s + 256;
    float* einv_s = dtv_s + 256;

    int bid = blockIdx.x;
    int h = bid % NH_;
    int bch = bid / NH_;
    int ch = bch % NC_;
    int b = bch / NC_;
    int tid = threadIdx.x;
    int wid = tid >> 5, lane = tid & 31;
    int wm = wid >> 1, wn = wid & 1;
    int grp = lane >> 2, tig = lane & 3;
    int t = tid;

    const float* xbc = g_xBC + (size_t)(b * L_ + ch * CH_) * CDIM_;
    const float* cbrow = g_CB + ((size_t)(b * NC_ + ch) * CH_ + t) * CH_;
    const float* isb = g_is + (size_t)bid * HD_ * DS_;
    int ab = bid * CH_;

    for (int slot = tid; slot < 4096; slot += 256) {
        int row = slot >> 4, p4 = (slot & 15) << 2;
        float4 v = *(const float4*)(xbc + (size_t)row * CDIM_ + h * HD_ + p4);
        float4 o;
        o.x = f2tf32f(v.x); o.y = f2tf32f(v.y);
        o.z = f2tf32f(v.z); o.w = f2tf32f(v.w);
        *(float4*)&x_s[row * 72 + p4] = o;
    }
    for (int slot = tid; slot < 2048; slot += 256) {
        int p = slot & 63, ng = (slot >> 6) << 2;
        float4 v = *(const float4*)(isb + (size_t)p * DS_ + ng);
        st_s[(ng + 0) * 72 + p] = f2tf32f(v.x);
        st_s[(ng + 1) * 72 + p] = f2tf32f(v.y);
        st_s[(ng + 2) * 72 + p] = f2tf32f(v.z);
        st_s[(ng + 3) * 72 + p] = f2tf32f(v.w);
    }
    acs_s[tid] = g_Acs[(size_t)ab + tid];
    dtv_s[tid] = g_dtv[(size_t)(b * L_ + ch * CH_ + tid) * NH_ + h];

    float acc[4][4][4];
#pragma unroll
    for (int mt = 0; mt < 4; mt++)
#pragma unroll
        for (int nt = 0; nt < 4; nt++)
#pragma unroll
            for (int i = 0; i < 4; i++) acc[mt][nt][i] = 0.f;

    for (int k0 = 0; k0 < CH_; k0 += 64) {
        __syncthreads();
        if (tid < 64) {
            int sb = k0 + (tid & 0x30);
            einv_s[tid] = __expf(fminf(acs_s[sb] - acs_s[k0 + tid], 80.f));
        }
        __syncthreads();
#pragma unroll
        for (int sub = 0; sub < 4; sub++) {
            int sbase = k0 + sub * 16;
            if (t >= sbase) {
                float et = __expf(acs_s[t] - acs_s[sbase]);
#pragma unroll
                for (int jj = 0; jj < 16; jj += 4) {
                    float4 cb4 = *(const float4*)(cbrow + sbase + jj);
                    int s0q = sbase + jj;
                    float4 o;
                    o.x = (s0q + 0 <= t) ? f2tf32f(et * einv_s[sub * 16 + jj + 0] * cb4.x * dtv_s[s0q + 0]) : 0.f;
                    o.y = (s0q + 1 <= t) ? f2tf32f(et * einv_s[sub * 16 + jj + 1] * cb4.y * dtv_s[s0q + 1]) : 0.f;
                    o.z = (s0q + 2 <= t) ? f2tf32f(et * einv_s[sub * 16 + jj + 2] * cb4.z * dtv_s[s0q + 2]) : 0.f;
                    o.w = (s0q + 3 <= t) ? f2tf32f(et * einv_s[sub * 16 + jj + 3] * cb4.w * dtv_s[s0q + 3]) : 0.f;
                    *(float4*)&w_s[t * 68 + sub * 16 + jj] = o;
                }
            } else {
                float4 z4 = {0.f, 0.f, 0.f, 0.f};
#pragma unroll
                for (int jj = 0; jj < 16; jj += 4)
                    *(float4*)&w_s[t * 68 + sub * 16 + jj] = z4;
            }
        }
        __syncthreads();
        if (wm * 64 + 63 >= k0) {
#pragma unroll
            for (int ks = 0; ks < 8; ks++) {
                uint32_t a[4][4], bfr[4][2];
#pragma unroll
                for (int mt = 0; mt < 4; mt++) {
                    int r0 = wm * 64 + mt * 16 + grp;
                    a[mt][0] = __float_as_uint(w_s[r0 * 68 + ks * 8 + tig]);
                    a[mt][1] = __float_as_uint(w_s[(r0 + 8) * 68 + ks * 8 + tig]);
                    a[mt][2] = __float_as_uint(w_s[r0 * 68 + ks * 8 + tig + 4]);
                    a[mt][3] = __float_as_uint(w_s[(r0 + 8) * 68 + ks * 8 + tig + 4]);
                }
#pragma unroll
                for (int nt = 0; nt < 4; nt++) {
                    int cc = wn * 32 + nt * 8 + grp;
                    bfr[nt][0] = __float_as_uint(x_s[(k0 + ks * 8 + tig) * 72 + cc]);
                    bfr[nt][1] = __float_as_uint(x_s[(k0 + ks * 8 + tig + 4) * 72 + cc]);
                }
#pragma unroll
                for (int mt = 0; mt < 4; mt++)
#pragma unroll
                    for (int nt = 0; nt < 4; nt++)
                        MMA_TF32(acc[mt][nt], a[mt][0], a[mt][1], a[mt][2], a[mt][3],
                                 bfr[nt][0], bfr[nt][1]);
            }
        }
    }

    float et0 = __expf(acs_s[t]);
    for (int n0 = 0; n0 < DS_; n0 += 64) {
        __syncthreads();
#pragma unroll
        for (int j = 0; j < 64; j += 4) {
            float4 c4 = *(const float4*)(xbc + (size_t)t * CDIM_ + DI_ + DS_ + n0 + j);
            float4 o;
            o.x = f2tf32f(c4.x * et0); o.y = f2tf32f(c4.y * et0);
            o.z = f2tf32f(c4.z * et0); o.w = f2tf32f(c4.w * et0);
            *(float4*)&w_s[t * 68 + j] = o;
        }
        __syncthreads();
#pragma unroll
        for (int ks = 0; ks < 8; ks++) {
            uint32_t a[4][4], bfr[4][2];
#pragma unroll
            for (int mt = 0; mt < 4; mt++) {
                int r0 = wm * 64 + mt * 16 + grp;
                a[mt][0] = __float_as_uint(w_s[r0 * 68 + ks * 8 + tig]);
                a[mt][1] = __float_as_uint(w_s[(r0 + 8) * 68 + ks * 8 + tig]);
                a[mt][2] = __float_as_uint(w_s[r0 * 68 + ks * 8 + tig + 4]);
                a[mt][3] = __float_as_uint(w_s[(r0 + 8) * 68 + ks * 8 + tig + 4]);
            }
#pragma unroll
            for (int nt = 0; nt < 4; nt++) {
                int cc = wn * 32 + nt * 8 + grp;
                bfr[nt][0] = __float_as_uint(st_s[(n0 + ks * 8 + tig) * 72 + cc]);
                bfr[nt][1] = __float_as_uint(st_s[(n0 + ks * 8 + tig + 4) * 72 + cc]);
            }
#pragma unroll
            for (int mt = 0; mt < 4; mt++)
#pragma unroll
                for (int nt = 0; nt < 4; nt++)
                    MMA_TF32(acc[mt][nt], a[mt][0], a[mt][1], a[mt][2], a[mt][3],
                             bfr[nt][0], bfr[nt][1]);
        }
    }

    float dsk = D_skip[h];
    size_t rowbase = (size_t)(b * L_ + ch * CH_);
#pragma unroll
    for (int mt = 0; mt < 4; mt++)
#pragma unroll
        for (int nt = 0; nt < 4; nt++) {
            int r0 = wm * 64 + mt * 16 + grp;
            int cc = wn * 32 + nt * 8 + tig * 2;
            float2 v0, v1;
            v0.x = acc[mt][nt][0] + dsk * x_s[r0 * 72 + cc];
            v0.y = acc[mt][nt][1] + dsk * x_s[r0 * 72 + cc + 1];
            v1.x = acc[mt][nt][2] + dsk * x_s[(r0 + 8) * 72 + cc];
            v1.y = acc[mt][nt][3] + dsk * x_s[(r0 + 8) * 72 + cc + 1];
            *(float2*)&g_y[(rowbase + r0) * DI_ + h * HD_ + cc]       = v0;
            *(float2*)&g_y[(rowbase + r0 + 8) * DI_ + h * HD_ + cc]   = v1;
        }
}

// ---------------- K9: gate + RMSNorm ----------------
__global__ void gate_kernel(const float* __restrict__ norm_w, float* __restrict__ out) {
    int row = blockIdx.x;
    int tid = threadIdx.x;
    int lane = tid & 31, wid = tid >> 5;
    __shared__ float yg_s[DI_];
    __shared__ float wsum[8];
    float ss = 0.f;
#pragma unroll
    for (int it = 0; it < DI_ / 1024; it++) {
        int i = it * 1024 + tid * 4;
        float4 yv = *(const float4*)(g_y + (size_t)row * DI_ + i);
        float4 z  = *(const float4*)(g_zx + (size_t)row * DIP_ + i);
        float4 yg;
        yg.x = yv.x * (z.x / (1.f + __expf(-z.x)));
        yg.y = yv.y * (z.y / (1.f + __expf(-z.y)));
        yg.z = yv.z * (z.z / (1.f + __expf(-z.z)));
        yg.w = yv.w * (z.w / (1.f + __expf(-z.w)));
        *(float4*)&yg_s[i] = yg;
        ss += yg.x * yg.x + yg.y * yg.y + yg.z * yg.z + yg.w * yg.w;
    }
#pragma unroll
    for (int off = 16; off > 0; off >>= 1)
        ss += __shfl_xor_sync(0xffffffffu, ss, off);
    if (lane == 0) wsum[wid] = ss;
    __syncthreads();
    float tot = wsum[0] + wsum[1] + wsum[2] + wsum[3]
              + wsum[4] + wsum[5] + wsum[6] + wsum[7];
    float r = rsqrtf(tot / (float)DI_ + 1e-5f);
#pragma unroll
    for (int it = 0; it < DI_ / 1024; it++) {
        int i = it * 1024 + tid * 4;
        float4 yg = *(float4*)&yg_s[i];
        float4 nw = *(const float4*)(norm_w + i);
        float4 o;
        o.x = yg.x * r * nw.x; o.y = yg.y * r * nw.y;
        o.z = yg.z * r * nw.z; o.w = yg.w * r * nw.w;
        *(float4*)(out + (size_t)row * DI_ + i) = o;
    }
}

// ---------------- launch ----------------
extern "C" void kernel_launch(void* const* d_in, const int* in_sizes, int n_in,
                              void* d_out, int out_size) {
    const float* u       = (const float*)d_in[0];
    const float* w_in    = (const float*)d_in[1];
    const float* conv_w  = (const float*)d_in[2];
    const float* conv_b  = (const float*)d_in[3];
    const float* dt_bias = (const float*)d_in[4];
    const float* A_log   = (const float*)d_in[5];
    const float* D_skip  = (const float*)d_in[6];
    const float* norm_w  = (const float*)d_in[7];
    float* out = (float*)d_out;

    const int Y_SMEM  = (256 * 68 + 256 * 72 + 128 * 72 + 256 + 256 + 64) * 4;
    const int CB_SMEM = 2 * 64 * 132 * 4;
    cudaFuncSetAttribute(y_kernel, cudaFuncAttributeMaxDynamicSharedMemorySize, Y_SMEM);
    cudaFuncSetAttribute(cb_kernel, cudaFuncAttributeMaxDynamicSharedMemorySize, CB_SMEM);
    cudaFuncSetAttribute(gemm_tf32_kernel, cudaFuncAttributeMaxDynamicSharedMemorySize, 3 * STG_);

    uconv_kernel<<<(B_ * L_ * DM_) / 4 / 256, 256>>>(u);
    wconv_kernel<<<(DM_ * GN_) / 4 / 256, 256>>>(w_in);
    gemm_tf32_kernel<<<dim3(GN_ / 256, (B_ * L_) / 128), 256, 3 * STG_>>>();
    dtg_part_kernel<<<dim3((B_ * L_) / 128, KSPL), 256>>>(u, w_in);
    dtr_kernel<<<(B_ * L_ * NH_) / 4 / 256, 256>>>(dt_bias);
    conv_kernel<<<(B_ * L_ / 2) * (CDIM_ / 4) / 256, 256>>>(conv_w, conv_b);
    acs_kernel<<<B_ * NC_ * NH_, CH_>>>(A_log);
    cb_kernel<<<dim3(4, 4, B_ * NC_), 256, CB_SMEM>>>();
    state_kernel<<<B_ * NC_ * NH_, 256>>>();
    rec_kernel<<<B_ * NH_ * 2, 256>>>();
    y_kernel<<<B_ * NC_ * NH_, 256, Y_SMEM>>>(D_skip);
    gate_kernel<<<B_ * L_, 256>>>(norm_w, out);
}

// round 17
// speedup vs baseline: 1.1004x; 1.0137x over previous
#include <cuda_runtime.h>
#include <cstdint>
#include <cmath>

#define B_    2
#define L_    2048
#define DM_   2048
#define DIP_  8512
#define DI_   4096
#define CDIM_ 4352
#define NH_   64
#define HD_   64
#define DS_   128
#define CH_   256
#define NC_   8
#define DCV   4
#define GN_   8448
#define KSPL  32

// ---------------- scratch ----------------
__device__ float g_zx  [(size_t)B_*L_*DIP_];
__device__ float g_xBC [(size_t)B_*L_*CDIM_];
__device__ float g_dtv [(size_t)B_*L_*NH_];
__device__ float g_dtp [(size_t)KSPL*B_*L_*NH_];
__device__ float g_Acs [(size_t)B_*NC_*NH_*CH_];
__device__ float g_CB  [(size_t)B_*NC_*CH_*CH_];
__device__ float g_st  [(size_t)B_*NC_*NH_*HD_*DS_];
__device__ float g_is  [(size_t)B_*NC_*NH_*HD_*DS_];
__device__ float g_y   [(size_t)B_*L_*DI_];
__device__ __align__(16) float g_ut[(size_t)B_*L_*DM_];
__device__ __align__(16) float g_wt[(size_t)DM_*GN_];

__device__ __forceinline__ float f2tf32f(float x) {
    uint32_t r;
    asm("cvt.rna.tf32.f32 %0, %1;" : "=r"(r) : "f"(x));
    return __uint_as_float(r);
}
__device__ __forceinline__ uint32_t smem_u32(const void* p) {
    uint32_t a;
    asm("{ .reg .u64 t; cvta.to.shared.u64 t, %1; cvt.u32.u64 %0, t; }" : "=r"(a) : "l"(p));
    return a;
}
__device__ __forceinline__ void cpa16(uint32_t dst, const void* src) {
    asm volatile("cp.async.cg.shared.global [%0], [%1], 16;" :: "r"(dst), "l"(src));
}
#define CPA_COMMIT() asm volatile("cp.async.commit_group;" ::: "memory")
#define CPA_WAIT1()  asm volatile("cp.async.wait_group 1;" ::: "memory")
#define MMA_TF32(acc, a0,a1,a2,a3, b0,b1)                                      \
    asm volatile("mma.sync.aligned.m16n8k8.row.col.f32.tf32.tf32.f32 "         \
        "{%0,%1,%2,%3}, {%4,%5,%6,%7}, {%8,%9}, {%0,%1,%2,%3};"                \
        : "+f"((acc)[0]), "+f"((acc)[1]), "+f"((acc)[2]), "+f"((acc)[3])       \
        : "r"(a0), "r"(a1), "r"(a2), "r"(a3), "r"(b0), "r"(b1))

// ---------------- K0a/K0b: tf32 pre-round ----------------
__global__ void uconv_kernel(const float* __restrict__ u) {
    size_t i = (size_t)blockIdx.x * 256 + threadIdx.x;
    float4 v = ((const float4*)u)[i];
    v.x = f2tf32f(v.x); v.y = f2tf32f(v.y);
    v.z = f2tf32f(v.z); v.w = f2tf32f(v.w);
    ((float4*)g_ut)[i] = v;
}
__global__ void wconv_kernel(const float* __restrict__ w) {
    size_t i = (size_t)blockIdx.x * 256 + threadIdx.x;
    int row = (int)(i / (GN_ / 4));
    int c4  = (int)(i % (GN_ / 4)) * 4;
    float4 v = *(const float4*)(w + (size_t)row * DIP_ + c4);
    v.x = f2tf32f(v.x); v.y = f2tf32f(v.y);
    v.z = f2tf32f(v.z); v.w = f2tf32f(v.w);
    *(float4*)(g_wt + (size_t)row * GN_ + c4) = v;
}

// ---------------- K1: main tf32 GEMM, 3-stage cp.async (proven best) ------
#define ASTG 18432
#define BSTG 33792
#define STG_ (ASTG + BSTG)
__global__ __launch_bounds__(256, 1) void gemm_tf32_kernel() {
    extern __shared__ char sal[];
    const int tid = threadIdx.x;
    const int m0 = blockIdx.y * 128;
    const int n0 = blockIdx.x * 256;
    const int lane = tid & 31, wid = tid >> 5;
    const int wm = wid >> 2, wn = wid & 3;
    const int grp = lane >> 2, tig = lane & 3;
    const uint32_t sbase = smem_u32(sal);
    const int NKT = DM_ / 32;

    float acc[4][8][4];
#pragma unroll
    for (int mt = 0; mt < 4; mt++)
#pragma unroll
        for (int nt = 0; nt < 8; nt++)
#pragma unroll
            for (int i = 0; i < 4; i++) acc[mt][nt][i] = 0.f;

    auto issue = [&](int buf, int kt) {
        uint32_t ab = sbase + buf * STG_;
        uint32_t bb = ab + ASTG;
#pragma unroll
        for (int i = 0; i < 4; i++) {
            int slot = tid + i * 256;
            int row = slot >> 3, c = slot & 7;
            cpa16(ab + row * 144 + c * 16,
                  g_ut + (size_t)(m0 + row) * DM_ + kt * 32 + c * 4);
        }
#pragma unroll
        for (int i = 0; i < 8; i++) {
            int slot = tid + i * 256;
            int row = slot >> 6, c = slot & 63;
            cpa16(bb + row * 1056 + c * 16,
                  g_wt + (size_t)(kt * 32 + row) * GN_ + n0 + c * 4);
        }
    };

    issue(0, 0); CPA_COMMIT();
    issue(1, 1); CPA_COMMIT();

    for (int kt = 0; kt < NKT; kt++) {
        CPA_WAIT1();
        __syncthreads();
        if (kt + 2 < NKT) issue((kt + 2) % 3, kt + 2);
        CPA_COMMIT();

        const float* As = (const float*)(sal + (kt % 3) * STG_);
        const float* Bs = (const float*)(sal + (kt % 3) * STG_ + ASTG);
#pragma unroll
        for (int ks = 0; ks < 4; ks++) {
            uint32_t a[4][4], b[8][2];
#pragma unroll
            for (int mt = 0; mt < 4; mt++) {
                int r0 = wm * 64 + mt * 16 + grp;
                a[mt][0] = __float_as_uint(As[r0 * 36 + ks * 8 + tig]);
                a[mt][1] = __float_as_uint(As[(r0 + 8) * 36 + ks * 8 + tig]);
                a[mt][2] = __float_as_uint(As[r0 * 36 + ks * 8 + tig + 4]);
                a[mt][3] = __float_as_uint(As[(r0 + 8) * 36 + ks * 8 + tig + 4]);
            }
#pragma unroll
            for (int nt = 0; nt < 8; nt++) {
                int cc = wn * 64 + nt * 8 + grp;
                b[nt][0] = __float_as_uint(Bs[(ks * 8 + tig) * 264 + cc]);
                b[nt][1] = __float_as_uint(Bs[(ks * 8 + tig + 4) * 264 + cc]);
            }
#pragma unroll
            for (int mt = 0; mt < 4; mt++)
#pragma unroll
                for (int nt = 0; nt < 8; nt++)
                    MMA_TF32(acc[mt][nt], a[mt][0], a[mt][1], a[mt][2], a[mt][3],
                             b[nt][0], b[nt][1]);
        }
        __syncthreads();
    }

#pragma unroll
    for (int mt = 0; mt < 4; mt++)
#pragma unroll
        for (int nt = 0; nt < 8; nt++) {
            int row = m0 + wm * 64 + mt * 16 + grp;
            int col = n0 + wn * 64 + nt * 8 + tig * 2;
            float2 v0, v1;
            v0.x = acc[mt][nt][0]; v0.y = acc[mt][nt][1];
            v1.x = acc[mt][nt][2]; v1.y = acc[mt][nt][3];
            *(float2*)&g_zx[(size_t)row * DIP_ + col]       = v0;
            *(float2*)&g_zx[(size_t)(row + 8) * DIP_ + col] = v1;
        }
}

// ---------------- K1b: dt GEMM K-split (proven) ----------------
__global__ __launch_bounds__(256) void dtg_part_kernel(const float* __restrict__ u,
                                                       const float* __restrict__ w) {
    __shared__ float u_s[32][136];
    __shared__ float w_s[32][68];
    const int m0 = blockIdx.x * 128;
    const int k0 = blockIdx.y * 64;
    const int tid = threadIdx.x;
    const int ti = tid >> 4, ni = tid & 15;
    float acc[8][4];
#pragma unroll
    for (int i = 0; i < 8; i++)
#pragma unroll
        for (int j = 0; j < 4; j++) acc[i][j] = 0.f;

    for (int kt = 0; kt < 64; kt += 32) {
        __syncthreads();
#pragma unroll
        for (int i = 0; i < 4; i++) {
            int slot = tid + i * 256;
            int row = slot >> 3, kq = (slot & 7) << 2;
            float4 v = *(const float4*)(u + (size_t)(m0 + row) * DM_ + k0 + kt + kq);
            u_s[kq + 0][row] = v.x; u_s[kq + 1][row] = v.y;
            u_s[kq + 2][row] = v.z; u_s[kq + 3][row] = v.w;
        }
#pragma unroll
        for (int i = 0; i < 2; i++) {
            int slot = tid + i * 256;
            int row = slot >> 4, c4 = (slot & 15) << 2;
            *(float4*)&w_s[row][c4] =
                *(const float4*)(w + (size_t)(k0 + kt + row) * DIP_ + DI_ + CDIM_ + c4);
        }
        __syncthreads();
#pragma unroll 8
        for (int k = 0; k < 32; k++) {
            float a[8], b[4];
            *(float4*)&a[0] = *(float4*)&u_s[k][ti * 8];
            *(float4*)&a[4] = *(float4*)&u_s[k][ti * 8 + 4];
            *(float4*)&b[0] = *(float4*)&w_s[k][ni * 4];
#pragma unroll
            for (int q = 0; q < 8; q++)
#pragma unroll
                for (int r = 0; r < 4; r++) acc[q][r] += a[q] * b[r];
        }
    }
    float* dst = g_dtp + ((size_t)blockIdx.y * (B_ * L_) + m0 + ti * 8) * NH_ + ni * 4;
#pragma unroll
    for (int q = 0; q < 8; q++)
        *(float4*)(dst + (size_t)q * NH_) = *(float4*)&acc[q][0];
}

__global__ void dtr_kernel(const float* __restrict__ dt_bias) {
    int i4 = (blockIdx.x * 256 + threadIdx.x) * 4;
    const int TOT = B_ * L_ * NH_;
    float4 x = *(const float4*)(dt_bias + (i4 & (NH_ - 1)));
#pragma unroll
    for (int s = 0; s < KSPL; s++) {
        float4 p = *(const float4*)(g_dtp + (size_t)s * TOT + i4);
        x.x += p.x; x.y += p.y; x.z += p.z; x.w += p.w;
    }
    float4 o;
    o.x = (x.x > 20.f) ? x.x : log1pf(expf(x.x));
    o.y = (x.y > 20.f) ? x.y : log1pf(expf(x.y));
    o.z = (x.z > 20.f) ? x.z : log1pf(expf(x.z));
    o.w = (x.w > 20.f) ? x.w : log1pf(expf(x.w));
    *(float4*)(g_dtv + i4) = o;
}

// ---------------- K2: conv + silu, 4 outputs/thread (1.75 loads/output) ----
__global__ void conv_kernel(const float* __restrict__ conv_w, const float* __restrict__ conv_b) {
    int idx = blockIdx.x * 256 + threadIdx.x;        // over (B*L/4)*(CDIM/4)
    int c4 = (idx % (CDIM_ / 4)) * 4;
    int blp = idx / (CDIM_ / 4);
    int b  = blp / (L_ / 4);
    int l0 = (blp % (L_ / 4)) * 4;
    size_t bl0 = (size_t)b * L_ + l0;

    float4 bias = *(const float4*)(conv_b + c4);
    float4 w0 = *(const float4*)(conv_w + (c4 + 0) * DCV);
    float4 w1 = *(const float4*)(conv_w + (c4 + 1) * DCV);
    float4 w2 = *(const float4*)(conv_w + (c4 + 2) * DCV);
    float4 w3 = *(const float4*)(conv_w + (c4 + 3) * DCV);

    // positions l0-3 .. l0+3 (7 loads for 4 outputs)
    float4 v[7];
#pragma unroll
    for (int j = 0; j < 7; j++) {
        int ls = l0 - 3 + j;
        if (ls >= 0)
            v[j] = *(const float4*)(g_zx + (bl0 - 3 + j) * DIP_ + DI_ + c4);
        else
            v[j] = make_float4(0.f, 0.f, 0.f, 0.f);
    }

    float4 a[4];
#pragma unroll
    for (int o = 0; o < 4; o++) a[o] = bias;
#pragma unroll
    for (int k = 0; k < DCV; k++) {
        float wk0 = (&w0.x)[k], wk1 = (&w1.x)[k], wk2 = (&w2.x)[k], wk3 = (&w3.x)[k];
#pragma unroll
        for (int o = 0; o < 4; o++) {
            a[o].x += v[k + o].x * wk0; a[o].y += v[k + o].y * wk1;
            a[o].z += v[k + o].z * wk2; a[o].w += v[k + o].w * wk3;
        }
    }
#pragma unroll
    for (int o = 0; o < 4; o++) {
        a[o].x = a[o].x / (1.f + __expf(-a[o].x));
        a[o].y = a[o].y / (1.f + __expf(-a[o].y));
        a[o].z = a[o].z / (1.f + __expf(-a[o].z));
        a[o].w = a[o].w / (1.f + __expf(-a[o].w));
        *(float4*)(g_xBC + (bl0 + o) * CDIM_ + c4) = a[o];
    }
}

// ---------------- K4: cumsum ----------------
__global__ void acs_kernel(const float* __restrict__ A_log) {
    int blk = blockIdx.x;
    int h = blk % NH_;
    int bc = blk / NH_;
    int c = bc % NC_;
    int b = bc / NC_;
    int t = threadIdx.x;
    __shared__ float s[CH_];
    float A = -__expf(A_log[h]);
    s[t] = g_dtv[(size_t)(b * L_ + c * CH_ + t) * NH_ + h] * A;
    __syncthreads();
    for (int off = 1; off < CH_; off <<= 1) {
        float v = (t >= off) ? s[t - off] : 0.f;
        __syncthreads();
        s[t] += v;
        __syncthreads();
    }
    g_Acs[(size_t)blk * CH_ + t] = s[t];
}

// ---------------- K5: CB via tf32 mma (proven) ----------------
__global__ __launch_bounds__(256, 1) void cb_kernel() {
    extern __shared__ float cbs[];
    float* C_s = cbs;
    float* B_s = cbs + 64 * 132;
    int z = blockIdx.z;
    int b = z / NC_, c = z % NC_;
    int t0 = blockIdx.y * 64, s0 = blockIdx.x * 64;
    int tid = threadIdx.x;
    int wid = tid >> 5, lane = tid & 31;
    int wm = wid >> 2, wn = wid & 3;
    int grp = lane >> 2, tig = lane & 3;
    const float* xbase = g_xBC + (size_t)(b * L_ + c * CH_) * CDIM_;

#pragma unroll
    for (int i = 0; i < 8; i++) {
        int slot = tid + i * 256;
        int row = slot >> 5, c4 = (slot & 31) << 2;
        float4 cv = *(const float4*)(xbase + (size_t)(t0 + row) * CDIM_ + DI_ + DS_ + c4);
        float4 bv = *(const float4*)(xbase + (size_t)(s0 + row) * CDIM_ + DI_ + c4);
        float4 co, bo;
        co.x = f2tf32f(cv.x); co.y = f2tf32f(cv.y); co.z = f2tf32f(cv.z); co.w = f2tf32f(cv.w);
        bo.x = f2tf32f(bv.x); bo.y = f2tf32f(bv.y); bo.z = f2tf32f(bv.z); bo.w = f2tf32f(bv.w);
        *(float4*)&C_s[row * 132 + c4] = co;
        *(float4*)&B_s[row * 132 + c4] = bo;
    }
    __syncthreads();

    float acc[2][2][4];
#pragma unroll
    for (int mt = 0; mt < 2; mt++)
#pragma unroll
        for (int nt = 0; nt < 2; nt++)
#pragma unroll
            for (int i = 0; i < 4; i++) acc[mt][nt][i] = 0.f;

#pragma unroll
    for (int ks = 0; ks < 16; ks++) {
        uint32_t a[2][4], bf[2][2];
#pragma unroll
        for (int mt = 0; mt < 2; mt++) {
            int r0 = wm * 32 + mt * 16 + grp;
            a[mt][0] = __float_as_uint(C_s[r0 * 132 + ks * 8 + tig]);
            a[mt][1] = __float_as_uint(C_s[(r0 + 8) * 132 + ks * 8 + tig]);
            a[mt][2] = __float_as_uint(C_s[r0 * 132 + ks * 8 + tig + 4]);
            a[mt][3] = __float_as_uint(C_s[(r0 + 8) * 132 + ks * 8 + tig + 4]);
        }
#pragma unroll
        for (int nt = 0; nt < 2; nt++) {
            int cc = wn * 16 + nt * 8 + grp;
            bf[nt][0] = __float_as_uint(B_s[cc * 132 + ks * 8 + tig]);
            bf[nt][1] = __float_as_uint(B_s[cc * 132 + ks * 8 + tig + 4]);
        }
#pragma unroll
        for (int mt = 0; mt < 2; mt++)
#pragma unroll
            for (int nt = 0; nt < 2; nt++)
                MMA_TF32(acc[mt][nt], a[mt][0], a[mt][1], a[mt][2], a[mt][3],
                         bf[nt][0], bf[nt][1]);
    }

#pragma unroll
    for (int mt = 0; mt < 2; mt++)
#pragma unroll
        for (int nt = 0; nt < 2; nt++) {
            int r = t0 + wm * 32 + mt * 16 + grp;
            int col = s0 + wn * 16 + nt * 8 + tig * 2;
            float2 v0, v1;
            v0.x = acc[mt][nt][0]; v0.y = acc[mt][nt][1];
            v1.x = acc[mt][nt][2]; v1.y = acc[mt][nt][3];
            *(float2*)&g_CB[((size_t)z * CH_ + r) * CH_ + col]     = v0;
            *(float2*)&g_CB[((size_t)z * CH_ + r + 8) * CH_ + col] = v1;
        }
}

// ---------------- K6: chunk states via tf32 mma (proven) ----------------
__global__ __launch_bounds__(256) void state_kernel() {
    __shared__ float wx_s[32][72];
    __shared__ float Bt_s[32][136];
    __shared__ float wv[32];
    int bid = blockIdx.x;
    int h = bid % NH_;
    int bc = bid / NH_;
    int c = bc % NC_;
    int b = bc / NC_;
    int tid = threadIdx.x;
    int wid = tid >> 5, lane = tid & 31;
    int wm = wid >> 2, wn = wid & 3;
    int grp = lane >> 2, tig = lane & 3;
    const float* xbc = g_xBC + (size_t)(b * L_ + c * CH_) * CDIM_;
    int ab = ((b * NC_ + c) * NH_ + h) * CH_;
    float acsLast = g_Acs[(size_t)ab + CH_ - 1];

    float acc[2][4][4];
#pragma unroll
    for (int mt = 0; mt < 2; mt++)
#pragma unroll
        for (int nt = 0; nt < 4; nt++)
#pragma unroll
            for (int i = 0; i < 4; i++) acc[mt][nt][i] = 0.f;

    for (int kt = 0; kt < CH_; kt += 32) {
        __syncthreads();
        if (tid < 32) {
            int r = kt + tid;
            wv[tid] = __expf(acsLast - g_Acs[(size_t)ab + r]) *
                      g_dtv[(size_t)(b * L_ + c * CH_ + r) * NH_ + h];
        }
        __syncthreads();
#pragma unroll
        for (int i = 0; i < 2; i++) {
            int slot = tid + i * 256;
            int row = slot >> 4, p4 = (slot & 15) << 2;
            float4 v = *(const float4*)(xbc + (size_t)(kt + row) * CDIM_ + h * HD_ + p4);
            float wgt = wv[row];
            float4 o;
            o.x = f2tf32f(v.x * wgt); o.y = f2tf32f(v.y * wgt);
            o.z = f2tf32f(v.z * wgt); o.w = f2tf32f(v.w * wgt);
            *(float4*)&wx_s[row][p4] = o;
        }
#pragma unroll
        for (int i = 0; i < 4; i++) {
            int slot = tid + i * 256;
            int row = slot >> 5, n4 = (slot & 31) << 2;
            float4 v = *(const float4*)(xbc + (size_t)(kt + row) * CDIM_ + DI_ + n4);
            float4 o;
            o.x = f2tf32f(v.x); o.y = f2tf32f(v.y);
            o.z = f2tf32f(v.z); o.w = f2tf32f(v.w);
            *(float4*)&Bt_s[row][n4] = o;
        }
        __syncthreads();
#pragma unroll
        for (int ks = 0; ks < 4; ks++) {
            uint32_t a[2][4], bf[4][2];
#pragma unroll
            for (int mt = 0; mt < 2; mt++) {
                int r0 = wm * 32 + mt * 16 + grp;
                a[mt][0] = __float_as_uint(wx_s[ks * 8 + tig][r0]);
                a[mt][1] = __float_as_uint(wx_s[ks * 8 + tig][r0 + 8]);
                a[mt][2] = __float_as_uint(wx_s[ks * 8 + tig + 4][r0]);
                a[mt][3] = __float_as_uint(wx_s[ks * 8 + tig + 4][r0 + 8]);
            }
#pragma unroll
            for (int nt = 0; nt < 4; nt++) {
                int cc = wn * 32 + nt * 8 + grp;
                bf[nt][0] = __float_as_uint(Bt_s[ks * 8 + tig][cc]);
                bf[nt][1] = __float_as_uint(Bt_s[ks * 8 + tig + 4][cc]);
            }
#pragma unroll
            for (int mt = 0; mt < 2; mt++)
#pragma unroll
                for (int nt = 0; nt < 4; nt++)
                    MMA_TF32(acc[mt][nt], a[mt][0], a[mt][1], a[mt][2], a[mt][3],
                             bf[nt][0], bf[nt][1]);
        }
    }
    size_t base = (size_t)bid * HD_ * DS_;
#pragma unroll
    for (int mt = 0; mt < 2; mt++)
#pragma unroll
        for (int nt = 0; nt < 4; nt++) {
            int p = wm * 32 + mt * 16 + grp;
            int n = wn * 32 + nt * 8 + tig * 2;
            float2 v0, v1;
            v0.x = acc[mt][nt][0]; v0.y = acc[mt][nt][1];
            v1.x = acc[mt][nt][2]; v1.y = acc[mt][nt][3];
            *(float2*)&g_st[base + (size_t)p * DS_ + n]       = v0;
            *(float2*)&g_st[base + (size_t)(p + 8) * DS_ + n] = v1;
        }
}

// ---------------- K7: recurrence (split 4x) ----------------
__global__ void rec_kernel() {
    int bid = blockIdx.x;              // (b*NH + h)*4 + quarter
    int quarter = bid & 3;
    int bh = bid >> 2;
    int h = bh % NH_;
    int b = bh / NH_;
    int tid = threadIdx.x;
    float S[8];
#pragma unroll
    for (int k = 0; k < 8; k++) S[k] = 0.f;
    for (int c = 0; c < NC_; c++) {
        int blk = (b * NC_ + c) * NH_ + h;
        size_t base = (size_t)blk * HD_ * DS_ + (size_t)quarter * 8 * 256;
        float ef = __expf(g_Acs[(size_t)blk * CH_ + CH_ - 1]);
#pragma unroll
        for (int k = 0; k < 8; k++) {
            size_t e = base + (size_t)k * 256 + tid;
            g_is[e] = S[k];
            S[k] = S[k] * ef + g_st[e];
        }
    }
}

// ---------------- K8: fused Y via tf32 mma (proven) ----------------
__global__ __launch_bounds__(256, 1) void y_kernel(const float* __restrict__ D_skip) {
    extern __shared__ float sm[];
    float* w_s   = sm;
    float* x_s   = w_s + 256 * 68;
    float* st_s  = x_s + 256 * 72;
    float* acs_s = st_s + 128 * 72;
    float* dtv_s = acs_s + 256;
    float* einv_s = dtv_s + 256;

    int bid = blockIdx.x;
    int h = bid % NH_;
    int bch = bid / NH_;
    int ch = bch % NC_;
    int b = bch / NC_;
    int tid = threadIdx.x;
    int wid = tid >> 5, lane = tid & 31;
    int wm = wid >> 1, wn = wid & 1;
    int grp = lane >> 2, tig = lane & 3;
    int t = tid;

    const float* xbc = g_xBC + (size_t)(b * L_ + ch * CH_) * CDIM_;
    const float* cbrow = g_CB + ((size_t)(b * NC_ + ch) * CH_ + t) * CH_;
    const float* isb = g_is + (size_t)bid * HD_ * DS_;
    int ab = bid * CH_;

    for (int slot = tid; slot < 4096; slot += 256) {
        int row = slot >> 4, p4 = (slot & 15) << 2;
        float4 v = *(const float4*)(xbc + (size_t)row * CDIM_ + h * HD_ + p4);
        float4 o;
        o.x = f2tf32f(v.x); o.y = f2tf32f(v.y);
        o.z = f2tf32f(v.z); o.w = f2tf32f(v.w);
        *(float4*)&x_s[row * 72 + p4] = o;
    }
    for (int slot = tid; slot < 2048; slot += 256) {
        int p = slot & 63, ng = (slot >> 6) << 2;
        float4 v = *(const float4*)(isb + (size_t)p * DS_ + ng);
        st_s[(ng + 0) * 72 + p] = f2tf32f(v.x);
        st_s[(ng + 1) * 72 + p] = f2tf32f(v.y);
        st_s[(ng + 2) * 72 + p] = f2tf32f(v.z);
        st_s[(ng + 3) * 72 + p] = f2tf32f(v.w);
    }
    acs_s[tid] = g_Acs[(size_t)ab + tid];
    dtv_s[tid] = g_dtv[(size_t)(b * L_ + ch * CH_ + tid) * NH_ + h];

    float acc[4][4][4];
#pragma unroll
    for (int mt = 0; mt < 4; mt++)
#pragma unroll
        for (int nt = 0; nt < 4; nt++)
#pragma unroll
            for (int i = 0; i < 4; i++) acc[mt][nt][i] = 0.f;

    for (int k0 = 0; k0 < CH_; k0 += 64) {
        __syncthreads();
        if (tid < 64) {
            int sb = k0 + (tid & 0x30);
            einv_s[tid] = __expf(fminf(acs_s[sb] - acs_s[k0 + tid], 80.f));
        }
        __syncthreads();
#pragma unroll
        for (int sub = 0; sub < 4; sub++) {
            int sbase = k0 + sub * 16;
            if (t >= sbase) {
                float et = __expf(acs_s[t] - acs_s[sbase]);
#pragma unroll
                for (int jj = 0; jj < 16; jj += 4) {
                    float4 cb4 = *(const float4*)(cbrow + sbase + jj);
                    int s0q = sbase + jj;
                    float4 o;
                    o.x = (s0q + 0 <= t) ? f2tf32f(et * einv_s[sub * 16 + jj + 0] * cb4.x * dtv_s[s0q + 0]) : 0.f;
                    o.y = (s0q + 1 <= t) ? f2tf32f(et * einv_s[sub * 16 + jj + 1] * cb4.y * dtv_s[s0q + 1]) : 0.f;
                    o.z = (s0q + 2 <= t) ? f2tf32f(et * einv_s[sub * 16 + jj + 2] * cb4.z * dtv_s[s0q + 2]) : 0.f;
                    o.w = (s0q + 3 <= t) ? f2tf32f(et * einv_s[sub * 16 + jj + 3] * cb4.w * dtv_s[s0q + 3]) : 0.f;
                    *(float4*)&w_s[t * 68 + sub * 16 + jj] = o;
                }
            } else {
                float4 z4 = {0.f, 0.f, 0.f, 0.f};
#pragma unroll
                for (int jj = 0; jj < 16; jj += 4)
                    *(float4*)&w_s[t * 68 + sub * 16 + jj] = z4;
            }
        }
        __syncthreads();
        if (wm * 64 + 63 >= k0) {
#pragma unroll
            for (int ks = 0; ks < 8; ks++) {
                uint32_t a[4][4], bfr[4][2];
#pragma unroll
                for (int mt = 0; mt < 4; mt++) {
                    int r0 = wm * 64 + mt * 16 + grp;
                    a[mt][0] = __float_as_uint(w_s[r0 * 68 + ks * 8 + tig]);
                    a[mt][1] = __float_as_uint(w_s[(r0 + 8) * 68 + ks * 8 + tig]);
                    a[mt][2] = __float_as_uint(w_s[r0 * 68 + ks * 8 + tig + 4]);
                    a[mt][3] = __float_as_uint(w_s[(r0 + 8) * 68 + ks * 8 + tig + 4]);
                }
#pragma unroll
                for (int nt = 0; nt < 4; nt++) {
                    int cc = wn * 32 + nt * 8 + grp;
                    bfr[nt][0] = __float_as_uint(x_s[(k0 + ks * 8 + tig) * 72 + cc]);
                    bfr[nt][1] = __float_as_uint(x_s[(k0 + ks * 8 + tig + 4) * 72 + cc]);
                }
#pragma unroll
                for (int mt = 0; mt < 4; mt++)
#pragma unroll
                    for (int nt = 0; nt < 4; nt++)
                        MMA_TF32(acc[mt][nt], a[mt][0], a[mt][1], a[mt][2], a[mt][3],
                                 bfr[nt][0], bfr[nt][1]);
            }
        }
    }

    float et0 = __expf(acs_s[t]);
    for (int n0 = 0; n0 < DS_; n0 += 64) {
        __syncthreads();
#pragma unroll
        for (int j = 0; j < 64; j += 4) {
            float4 c4 = *(const float4*)(xbc + (size_t)t * CDIM_ + DI_ + DS_ + n0 + j);
            float4 o;
            o.x = f2tf32f(c4.x * et0); o.y = f2tf32f(c4.y * et0);
            o.z = f2tf32f(c4.z * et0); o.w = f2tf32f(c4.w * et0);
            *(float4*)&w_s[t * 68 + j] = o;
        }
        __syncthreads();
#pragma unroll
        for (int ks = 0; ks < 8; ks++) {
            uint32_t a[4][4], bfr[4][2];
#pragma unroll
            for (int mt = 0; mt < 4; mt++) {
                int r0 = wm * 64 + mt * 16 + grp;
                a[mt][0] = __float_as_uint(w_s[r0 * 68 + ks * 8 + tig]);
                a[mt][1] = __float_as_uint(w_s[(r0 + 8) * 68 + ks * 8 + tig]);
                a[mt][2] = __float_as_uint(w_s[r0 * 68 + ks * 8 + tig + 4]);
                a[mt][3] = __float_as_uint(w_s[(r0 + 8) * 68 + ks * 8 + tig + 4]);
            }
#pragma unroll
            for (int nt = 0; nt < 4; nt++) {
                int cc = wn * 32 + nt * 8 + grp;
                bfr[nt][0] = __float_as_uint(st_s[(n0 + ks * 8 + tig) * 72 + cc]);
                bfr[nt][1] = __float_as_uint(st_s[(n0 + ks * 8 + tig + 4) * 72 + cc]);
            }
#pragma unroll
            for (int mt = 0; mt < 4; mt++)
#pragma unroll
                for (int nt = 0; nt < 4; nt++)
                    MMA_TF32(acc[mt][nt], a[mt][0], a[mt][1], a[mt][2], a[mt][3],
                             bfr[nt][0], bfr[nt][1]);
        }
    }

    float dsk = D_skip[h];
    size_t rowbase = (size_t)(b * L_ + ch * CH_);
#pragma unroll
    for (int mt = 0; mt < 4; mt++)
#pragma unroll
        for (int nt = 0; nt < 4; nt++) {
            int r0 = wm * 64 + mt * 16 + grp;
            int cc = wn * 32 + nt * 8 + tig * 2;
            float2 v0, v1;
            v0.x = acc[mt][nt][0] + dsk * x_s[r0 * 72 + cc];
            v0.y = acc[mt][nt][1] + dsk * x_s[r0 * 72 + cc + 1];
            v1.x = acc[mt][nt][2] + dsk * x_s[(r0 + 8) * 72 + cc];
            v1.y = acc[mt][nt][3] + dsk * x_s[(r0 + 8) * 72 + cc + 1];
            *(float2*)&g_y[(rowbase + r0) * DI_ + h * HD_ + cc]       = v0;
            *(float2*)&g_y[(rowbase + r0 + 8) * DI_ + h * HD_ + cc]   = v1;
        }
}

// ---------------- K9: gate + RMSNorm ----------------
__global__ void gate_kernel(const float* __restrict__ norm_w, float* __restrict__ out) {
    int row = blockIdx.x;
    int tid = threadIdx.x;
    int lane = tid & 31, wid = tid >> 5;
    __shared__ float yg_s[DI_];
    __shared__ float wsum[8];
    float ss = 0.f;
#pragma unroll
    for (int it = 0; it < DI_ / 1024; it++) {
        int i = it * 1024 + tid * 4;
        float4 yv = *(const float4*)(g_y + (size_t)row * DI_ + i);
        float4 z  = *(const float4*)(g_zx + (size_t)row * DIP_ + i);
        float4 yg;
        yg.x = yv.x * (z.x / (1.f + __expf(-z.x)));
        yg.y = yv.y * (z.y / (1.f + __expf(-z.y)));
        yg.z = yv.z * (z.z / (1.f + __expf(-z.z)));
        yg.w = yv.w * (z.w / (1.f + __expf(-z.w)));
        *(float4*)&yg_s[i] = yg;
        ss += yg.x * yg.x + yg.y * yg.y + yg.z * yg.z + yg.w * yg.w;
    }
#pragma unroll
    for (int off = 16; off > 0; off >>= 1)
        ss += __shfl_xor_sync(0xffffffffu, ss, off);
    if (lane == 0) wsum[wid] = ss;
    __syncthreads();
    float tot = wsum[0] + wsum[1] + wsum[2] + wsum[3]
              + wsum[4] + wsum[5] + wsum[6] + wsum[7];
    float r = rsqrtf(tot / (float)DI_ + 1e-5f);
#pragma unroll
    for (int it = 0; it < DI_ / 1024; it++) {
        int i = it * 1024 + tid * 4;
        float4 yg = *(float4*)&yg_s[i];
        float4 nw = *(const float4*)(norm_w + i);
        float4 o;
        o.x = yg.x * r * nw.x; o.y = yg.y * r * nw.y;
        o.z = yg.z * r * nw.z; o.w = yg.w * r * nw.w;
        *(float4*)(out + (size_t)row * DI_ + i) = o;
    }
}

// ---------------- launch ----------------
extern "C" void kernel_launch(void* const* d_in, const int* in_sizes, int n_in,
                              void* d_out, int out_size) {
    const float* u       = (const float*)d_in[0];
    const float* w_in    = (const float*)d_in[1];
    const float* conv_w  = (const float*)d_in[2];
    const float* conv_b  = (const float*)d_in[3];
    const float* dt_bias = (const float*)d_in[4];
    const float* A_log   = (const float*)d_in[5];
    const float* D_skip  = (const float*)d_in[6];
    const float* norm_w  = (const float*)d_in[7];
    float* out = (float*)d_out;

    const int Y_SMEM  = (256 * 68 + 256 * 72 + 128 * 72 + 256 + 256 + 64) * 4;
    const int CB_SMEM = 2 * 64 * 132 * 4;
    cudaFuncSetAttribute(y_kernel, cudaFuncAttributeMaxDynamicSharedMemorySize, Y_SMEM);
    cudaFuncSetAttribute(cb_kernel, cudaFuncAttributeMaxDynamicSharedMemorySize, CB_SMEM);
    cudaFuncSetAttribute(gemm_tf32_kernel, cudaFuncAttributeMaxDynamicSharedMemorySize, 3 * STG_);

    uconv_kernel<<<(B_ * L_ * DM_) / 4 / 256, 256>>>(u);
    wconv_kernel<<<(DM_ * GN_) / 4 / 256, 256>>>(w_in);
    gemm_tf32_kernel<<<dim3(GN_ / 256, (B_ * L_) / 128), 256, 3 * STG_>>>();
    dtg_part_kernel<<<dim3((B_ * L_) / 128, KSPL), 256>>>(u, w_in);
    dtr_kernel<<<(B_ * L_ * NH_) / 4 / 256, 256>>>(dt_bias);
    conv_kernel<<<(B_ * L_ / 4) * (CDIM_ / 4) / 256, 256>>>(conv_w, conv_b);
    acs_kernel<<<B_ * NC_ * NH_, CH_>>>(A_log);
    cb_kernel<<<dim3(4, 4, B_ * NC_), 256, CB_SMEM>>>();
    state_kernel<<<B_ * NC_ * NH_, 256>>>();
    rec_kernel<<<B_ * NH_ * 4, 256>>>();
    y_kernel<<<B_ * NC_ * NH_, 256, Y_SMEM>>>(D_skip);
    gate_kernel<<<B_ * L_, 256>>>(norm_w, out);
}